// round 14
// baseline (speedup 1.0000x reference)
#include <cuda_runtime.h>
#include <cuda_fp16.h>

#define NN   50000
#define NE   800000
#define ET   (NE + NN)
#define INC  128
#define HID  32
#define H1   8
#define D1   256
#define D2   64
#define NCHP 4
#define CHN  (NN / NCHP)      // 12500 nodes per pipeline chunk

__device__ __forceinline__ float lrelu(float v) { return v > 0.f ? v : 0.2f * v; }

// ---- scratch ----
__device__ __half   g_h1[(size_t)NN * D1];
__device__ __half   g_out1[(size_t)NN * D1];
__device__ float    g_as1[NN * H1];
__device__ float    g_ad1[NN * H1];
__device__ __half   g_h2[(size_t)NN * D2];
__device__ float    g_as2[NN];
__device__ float    g_ad2[NN];

// CSR
__device__ int g_cnt[NN];
__device__ int g_row[NN + 1];
__device__ int g_cur[NN];
__device__ int g_csr_src[ET];

// ============================================================
// CSR build
// ============================================================
__global__ void hist(const int* __restrict__ ei) {
    int i = blockIdx.x * blockDim.x + threadIdx.x;
    if (i * 4 >= NE) return;
    int4 d = *(const int4*)&ei[NE + i * 4];
    atomicAdd(&g_cnt[d.x], 1);
    atomicAdd(&g_cnt[d.y], 1);
    atomicAdd(&g_cnt[d.z], 1);
    atomicAdd(&g_cnt[d.w], 1);
}
__global__ void scan_fused() {
    __shared__ int wsum[32];
    __shared__ int s_carry;
    const int CH = 2048;
    int t = threadIdx.x, lane = t & 31, wid = t >> 5;
    if (t == 0) s_carry = 0;
    __syncthreads();
    for (int chunk = 0; chunk < (NN + CH - 1) / CH; chunk++) {
        int i0 = chunk * CH + 2 * t;
        int v0 = (i0     < NN) ? g_cnt[i0]     + 1 : 0;
        int v1 = (i0 + 1 < NN) ? g_cnt[i0 + 1] + 1 : 0;
        int p = v0 + v1;
        int x = p;
#pragma unroll
        for (int o = 1; o < 32; o <<= 1) {
            int y = __shfl_up_sync(0xffffffffu, x, o);
            if (lane >= o) x += y;
        }
        if (lane == 31) wsum[wid] = x;
        __syncthreads();
        if (wid == 0) {
            int w = wsum[lane];
#pragma unroll
            for (int o = 1; o < 32; o <<= 1) {
                int y = __shfl_up_sync(0xffffffffu, w, o);
                if (lane >= o) w += y;
            }
            wsum[lane] = w;
        }
        __syncthreads();
        int base = s_carry + (wid ? wsum[wid - 1] : 0);
        int excl = base + x - p;
        if (i0     < NN) { g_row[i0]     = excl;      g_cur[i0]     = excl; }
        if (i0 + 1 < NN) { g_row[i0 + 1] = excl + v0; g_cur[i0 + 1] = excl + v0; }
        __syncthreads();
        if (t == blockDim.x - 1) s_carry = base + x;
        __syncthreads();
    }
    if (t == 0) g_row[NN] = ET;
}
__global__ void scatter(const int* __restrict__ ei) {
    int i = blockIdx.x * blockDim.x + threadIdx.x;
    if (i < NE / 2) {
        int2 s = *(const int2*)&ei[2 * i];
        int2 d = *(const int2*)&ei[NE + 2 * i];
        int p0 = atomicAdd(&g_cur[d.x], 1); g_csr_src[p0] = s.x;
        int p1 = atomicAdd(&g_cur[d.y], 1); g_csr_src[p1] = s.y;
    } else {
        int e = i - NE / 2;
        if (e < NN) {
            int p = atomicAdd(&g_cur[e], 1);
            g_csr_src[p] = e;
        }
    }
}

// ============================================================
// fp16 MMA helper (m16n8k16)
// ============================================================
__device__ __forceinline__ void mma_f16(float c[4], const unsigned a[4],
                                        const unsigned b[2]) {
    asm volatile(
        "mma.sync.aligned.m16n8k16.row.col.f32.f16.f16.f32 "
        "{%0,%1,%2,%3}, {%4,%5,%6,%7}, {%8,%9}, {%0,%1,%2,%3};"
        : "+f"(c[0]), "+f"(c[1]), "+f"(c[2]), "+f"(c[3])
        : "r"(a[0]), "r"(a[1]), "r"(a[2]), "r"(a[3]), "r"(b[0]), "r"(b[1]));
}

#define ASTRIDE 20
#define BSTRIDE 72

// ============================================================
// GEMM1 fused (fp16 HMMA): h1 = x @ W1 (fp16 out) + att scores.
// Register-staged double buffering of k-tiles.
// ============================================================
__global__ void gemm1_fused(const float* __restrict__ A, const float* __restrict__ B,
                            __half* __restrict__ C,
                            const float* __restrict__ atts,
                            const float* __restrict__ attd,
                            float* __restrict__ as_, float* __restrict__ ad_) {
    const int BM = 128, BN = 64, BK = 32, M = NN, N = D1, K = INC;
    const int NT = K / BK;
    __shared__ __half2 As2[BM][ASTRIDE];
    __shared__ __half2 Bs2[BK / 2][BSTRIDE];

    int t = threadIdx.x, warp = t >> 5, lane = t & 31;
    int wm = warp >> 1, wn = warp & 1;
    int g = lane >> 2, t4 = lane & 3;
    int row0 = blockIdx.y * BM, col0 = blockIdx.x * BN;

    float acc[2][4][4] = {};

    float4 va[4];
    float bl[4], bh[4];

    {
#pragma unroll
        for (int i = 0; i < 4; i++) {
            int idx = t + i * 256;
            int r = idx >> 3, c4 = (idx & 7) * 4;
            int gr = row0 + r;
            va[i] = (gr < M) ? *(const float4*)&A[(size_t)gr * K + c4]
                             : make_float4(0.f, 0.f, 0.f, 0.f);
        }
#pragma unroll
        for (int i = 0; i < 4; i++) {
            int idx = t + i * 256;
            int kk = idx >> 6, n = idx & 63;
            bl[i] = B[(size_t)(2 * kk) * N + col0 + n];
            bh[i] = B[(size_t)(2 * kk + 1) * N + col0 + n];
        }
    }

    for (int it = 0; it < NT; it++) {
#pragma unroll
        for (int i = 0; i < 4; i++) {
            int idx = t + i * 256;
            int r = idx >> 3, c4 = (idx & 7) * 4;
            __half2 h0 = __floats2half2_rn(va[i].x, va[i].y);
            __half2 h1v = __floats2half2_rn(va[i].z, va[i].w);
            *(uint2*)&As2[r][c4 / 2] =
                make_uint2(*(unsigned*)&h0, *(unsigned*)&h1v);
        }
#pragma unroll
        for (int i = 0; i < 4; i++) {
            int idx = t + i * 256;
            int kk = idx >> 6, n = idx & 63;
            Bs2[kk][n] = __floats2half2_rn(bl[i], bh[i]);
        }
        __syncthreads();

        if (it + 1 < NT) {
            int kt = (it + 1) * BK;
#pragma unroll
            for (int i = 0; i < 4; i++) {
                int idx = t + i * 256;
                int r = idx >> 3, c4 = (idx & 7) * 4;
                int gr = row0 + r;
                va[i] = (gr < M) ? *(const float4*)&A[(size_t)gr * K + kt + c4]
                                 : make_float4(0.f, 0.f, 0.f, 0.f);
            }
#pragma unroll
            for (int i = 0; i < 4; i++) {
                int idx = t + i * 256;
                int kk = idx >> 6, n = idx & 63;
                bl[i] = B[(size_t)(kt + 2 * kk) * N + col0 + n];
                bh[i] = B[(size_t)(kt + 2 * kk + 1) * N + col0 + n];
            }
        }

#pragma unroll
        for (int k0 = 0; k0 < BK; k0 += 16) {
            int kk = k0 >> 1;
            unsigned a[2][4], b[4][2];
#pragma unroll
            for (int mi = 0; mi < 2; mi++) {
                int mb = wm * 32 + mi * 16;
                a[mi][0] = *(const unsigned*)&As2[mb + g][kk + t4];
                a[mi][1] = *(const unsigned*)&As2[mb + 8 + g][kk + t4];
                a[mi][2] = *(const unsigned*)&As2[mb + g][kk + 4 + t4];
                a[mi][3] = *(const unsigned*)&As2[mb + 8 + g][kk + 4 + t4];
            }
#pragma unroll
            for (int ni = 0; ni < 4; ni++) {
                int nb = wn * 32 + ni * 8;
                b[ni][0] = *(const unsigned*)&Bs2[kk + t4][nb + g];
                b[ni][1] = *(const unsigned*)&Bs2[kk + 4 + t4][nb + g];
            }
#pragma unroll
            for (int mi = 0; mi < 2; mi++)
#pragma unroll
                for (int ni = 0; ni < 4; ni++)
                    mma_f16(acc[mi][ni], a[mi], b[ni]);
        }
        __syncthreads();
    }

#pragma unroll
    for (int mi = 0; mi < 2; mi++)
#pragma unroll
        for (int ni = 0; ni < 4; ni++) {
            int col = col0 + wn * 32 + ni * 8 + t4 * 2;
            int r0 = row0 + wm * 32 + mi * 16 + g, r1 = r0 + 8;
            if (r0 < M)
                *(__half2*)&C[(size_t)r0 * N + col] =
                    __floats2half2_rn(acc[mi][ni][0], acc[mi][ni][1]);
            if (r1 < M)
                *(__half2*)&C[(size_t)r1 * N + col] =
                    __floats2half2_rn(acc[mi][ni][2], acc[mi][ni][3]);
        }

    int hidx = (col0 + wn * 32) >> 5;
    const float* aw = atts + hidx * HID;
    const float* dw = attd + hidx * HID;
#pragma unroll
    for (int mi = 0; mi < 2; mi++) {
        float ss0 = 0.f, dd0 = 0.f, ss1 = 0.f, dd1 = 0.f;
#pragma unroll
        for (int ni = 0; ni < 4; ni++) {
            int c = ni * 8 + t4 * 2;
            float a0 = aw[c], a1 = aw[c + 1];
            float d0 = dw[c], d1 = dw[c + 1];
            ss0 += acc[mi][ni][0] * a0 + acc[mi][ni][1] * a1;
            dd0 += acc[mi][ni][0] * d0 + acc[mi][ni][1] * d1;
            ss1 += acc[mi][ni][2] * a0 + acc[mi][ni][3] * a1;
            dd1 += acc[mi][ni][2] * d0 + acc[mi][ni][3] * d1;
        }
#pragma unroll
        for (int o = 1; o < 4; o <<= 1) {
            ss0 += __shfl_xor_sync(0xffffffffu, ss0, o);
            dd0 += __shfl_xor_sync(0xffffffffu, dd0, o);
            ss1 += __shfl_xor_sync(0xffffffffu, ss1, o);
            dd1 += __shfl_xor_sync(0xffffffffu, dd1, o);
        }
        if (t4 == 0) {
            int r0 = row0 + wm * 32 + mi * 16 + g, r1 = r0 + 8;
            if (r0 < M) { as_[r0 * H1 + hidx] = ss0; ad_[r0 * H1 + hidx] = dd0; }
            if (r1 < M) { as_[r1 * H1 + hidx] = ss1; ad_[r1 * H1 + hidx] = dd1; }
        }
    }
}

// ============================================================
// GEMM2 fused (fp16 HMMA), row-range parametrized (simple loop).
// ============================================================
__global__ void gemm2_fused(const __half* __restrict__ A, const float* __restrict__ B,
                            __half* __restrict__ C,
                            const float* __restrict__ atts,
                            const float* __restrict__ attd,
                            float* __restrict__ as_, float* __restrict__ ad_,
                            int row_base, int nrows) {
    const int BM = 128, BN = 64, BK = 32, N = D2, K = D1;
    const int Mlim = row_base + nrows;
    __shared__ __half2 As2[BM][ASTRIDE];
    __shared__ __half2 Bs2[BK / 2][BSTRIDE];
    __shared__ float sS[BM][2], sD[BM][2];

    int t = threadIdx.x, warp = t >> 5, lane = t & 31;
    int wm = warp >> 1, wn = warp & 1;
    int g = lane >> 2, t4 = lane & 3;
    int row0 = row_base + blockIdx.y * BM;

    float acc[2][4][4] = {};

    for (int kt = 0; kt < K; kt += BK) {
#pragma unroll
        for (int i = 0; i < 2; i++) {
            int idx = t + i * 256;
            int r = idx >> 2, c8 = (idx & 3) * 8;
            int gr = row0 + r;
            uint4 raw = (gr < Mlim) ? *(const uint4*)&A[(size_t)gr * K + kt + c8]
                                    : make_uint4(0, 0, 0, 0);
            *(uint2*)&As2[r][c8 / 2]     = make_uint2(raw.x, raw.y);
            *(uint2*)&As2[r][c8 / 2 + 2] = make_uint2(raw.z, raw.w);
        }
#pragma unroll
        for (int i = 0; i < 4; i++) {
            int idx = t + i * 256;
            int kk = idx >> 6, n = idx & 63;
            float lo = B[(size_t)(kt + 2 * kk) * N + n];
            float hi = B[(size_t)(kt + 2 * kk + 1) * N + n];
            Bs2[kk][n] = __floats2half2_rn(lo, hi);
        }
        __syncthreads();
#pragma unroll
        for (int k0 = 0; k0 < BK; k0 += 16) {
            int kk = k0 >> 1;
            unsigned a[2][4], b[4][2];
#pragma unroll
            for (int mi = 0; mi < 2; mi++) {
                int mb = wm * 32 + mi * 16;
                a[mi][0] = *(const unsigned*)&As2[mb + g][kk + t4];
                a[mi][1] = *(const unsigned*)&As2[mb + 8 + g][kk + t4];
                a[mi][2] = *(const unsigned*)&As2[mb + g][kk + 4 + t4];
                a[mi][3] = *(const unsigned*)&As2[mb + 8 + g][kk + 4 + t4];
            }
#pragma unroll
            for (int ni = 0; ni < 4; ni++) {
                int nb = wn * 32 + ni * 8;
                b[ni][0] = *(const unsigned*)&Bs2[kk + t4][nb + g];
                b[ni][1] = *(const unsigned*)&Bs2[kk + 4 + t4][nb + g];
            }
#pragma unroll
            for (int mi = 0; mi < 2; mi++)
#pragma unroll
                for (int ni = 0; ni < 4; ni++)
                    mma_f16(acc[mi][ni], a[mi], b[ni]);
        }
        __syncthreads();
    }

#pragma unroll
    for (int mi = 0; mi < 2; mi++)
#pragma unroll
        for (int ni = 0; ni < 4; ni++) {
            int col = wn * 32 + ni * 8 + t4 * 2;
            int r0 = row0 + wm * 32 + mi * 16 + g, r1 = r0 + 8;
            if (r0 < Mlim)
                *(__half2*)&C[(size_t)r0 * N + col] =
                    __floats2half2_rn(acc[mi][ni][0], acc[mi][ni][1]);
            if (r1 < Mlim)
                *(__half2*)&C[(size_t)r1 * N + col] =
                    __floats2half2_rn(acc[mi][ni][2], acc[mi][ni][3]);
        }

#pragma unroll
    for (int mi = 0; mi < 2; mi++) {
        float ss0 = 0.f, dd0 = 0.f, ss1 = 0.f, dd1 = 0.f;
#pragma unroll
        for (int ni = 0; ni < 4; ni++) {
            int c = wn * 32 + ni * 8 + t4 * 2;
            float a0 = atts[c], a1 = atts[c + 1];
            float d0 = attd[c], d1 = attd[c + 1];
            ss0 += acc[mi][ni][0] * a0 + acc[mi][ni][1] * a1;
            dd0 += acc[mi][ni][0] * d0 + acc[mi][ni][1] * d1;
            ss1 += acc[mi][ni][2] * a0 + acc[mi][ni][3] * a1;
            dd1 += acc[mi][ni][2] * d0 + acc[mi][ni][3] * d1;
        }
#pragma unroll
        for (int o = 1; o < 4; o <<= 1) {
            ss0 += __shfl_xor_sync(0xffffffffu, ss0, o);
            dd0 += __shfl_xor_sync(0xffffffffu, dd0, o);
            ss1 += __shfl_xor_sync(0xffffffffu, ss1, o);
            dd1 += __shfl_xor_sync(0xffffffffu, dd1, o);
        }
        if (t4 == 0) {
            int lr0 = wm * 32 + mi * 16 + g, lr1 = lr0 + 8;
            sS[lr0][wn] = ss0; sD[lr0][wn] = dd0;
            sS[lr1][wn] = ss1; sD[lr1][wn] = dd1;
        }
    }
    __syncthreads();
    if (t < BM) {
        int gr = row0 + t;
        if (gr < Mlim) {
            as_[gr] = sS[t][0] + sS[t][1];
            ad_[gr] = sD[t][0] + sD[t][1];
        }
    }
}

// ============================================================
// layer1 aggregation: warp per node, own-head exp, half2 pair
// accumulation, L2-only (__ldcg) row gathers.
// ============================================================
__global__ void aggr1(const float* __restrict__ b1, int node_base, int nnodes) {
    int gw   = (blockIdx.x * blockDim.x + threadIdx.x) >> 5;
    int lane = threadIdx.x & 31;
    if (gw >= nnodes) return;
    int node = node_base + gw;
    int head = lane >> 2;

    float adh = g_ad1[node * H1 + head];
    int beg = g_row[node], end = g_row[node + 1];

    float den = 0.f;
    float acc[8] = {};
    const __half* hbase = g_h1 + lane * 8;

    int j = beg;
    int s[4];
    bool cur = (j + 3 < end);
    if (cur) {
#pragma unroll
        for (int k = 0; k < 4; k++) s[k] = __ldg(&g_csr_src[j + k]);
    }
    while (cur) {
        int jn = j + 4;
        bool nxt = (jn + 3 < end);
        int sn[4];
        if (nxt) {
#pragma unroll
            for (int k = 0; k < 4; k++) sn[k] = __ldg(&g_csr_src[jn + k]);
        }
        uint4 r[4];
#pragma unroll
        for (int k = 0; k < 4; k++)
            r[k] = __ldcg((const uint4*)(hbase + (size_t)s[k] * D1));
        float e[4];
#pragma unroll
        for (int k = 0; k < 4; k++)
            e[k] = __expf(lrelu(__ldg(&g_as1[s[k] * H1 + head]) + adh));
        den += (e[0] + e[1]) + (e[2] + e[3]);
        __half2 eh[4];
#pragma unroll
        for (int k = 0; k < 4; k++)
            eh[k] = __float2half2_rn(e[k]);
        const __half2* p0 = (const __half2*)&r[0];
        const __half2* p1 = (const __half2*)&r[1];
        const __half2* p2 = (const __half2*)&r[2];
        const __half2* p3 = (const __half2*)&r[3];
#pragma unroll
        for (int q = 0; q < 4; q++) {
            __half2 t01 = __hfma2(p1[q], eh[1], __hmul2(p0[q], eh[0]));
            __half2 t23 = __hfma2(p3[q], eh[3], __hmul2(p2[q], eh[2]));
            float2 f01 = __half22float2(t01);
            float2 f23 = __half22float2(t23);
            acc[2 * q]     += f01.x + f23.x;
            acc[2 * q + 1] += f01.y + f23.y;
        }
        j = jn;
        cur = nxt;
#pragma unroll
        for (int k = 0; k < 4; k++) s[k] = sn[k];
    }
    for (; j < end; j++) {
        int s0 = __ldg(&g_csr_src[j]);
        float e0 = __expf(lrelu(__ldg(&g_as1[s0 * H1 + head]) + adh));
        den += e0;
        uint4 r0 = __ldcg((const uint4*)(hbase + (size_t)s0 * D1));
        const __half2* p = (const __half2*)&r0;
#pragma unroll
        for (int q = 0; q < 4; q++) {
            float2 f = __half22float2(p[q]);
            acc[2 * q]     += e0 * f.x;
            acc[2 * q + 1] += e0 * f.y;
        }
    }

    float inv = 1.f / (den + 1e-16f);
    const float* bb = b1 + lane * 8;
    __half2 o[4];
#pragma unroll
    for (int q = 0; q < 4; q++) {
        float f0 = fmaxf(acc[2 * q]     * inv + bb[2 * q],     0.f);
        float f1 = fmaxf(acc[2 * q + 1] * inv + bb[2 * q + 1], 0.f);
        o[q] = __floats2half2_rn(f0, f1);
    }
    *(uint4*)(g_out1 + (size_t)node * D1 + lane * 8) = *(uint4*)o;
}

// ---- layer2 aggregation: warp per node, __ldcg gathers ----
__global__ void aggr2(float* __restrict__ out, const float* __restrict__ b2) {
    int w    = (blockIdx.x * blockDim.x + threadIdx.x) >> 5;
    int lane = threadIdx.x & 31;
    if (w >= NN) return;
    float adh = g_ad2[w];
    int beg = g_row[w], end = g_row[w + 1];

    float den = 0.f;
    float2 acc = {0.f, 0.f};
    int j = beg;
    int s[4];
    bool cur = (j + 3 < end);
    if (cur) {
#pragma unroll
        for (int k = 0; k < 4; k++) s[k] = __ldg(&g_csr_src[j + k]);
    }
    while (cur) {
        int jn = j + 4;
        bool nxt = (jn + 3 < end);
        int sn[4];
        if (nxt) {
#pragma unroll
            for (int k = 0; k < 4; k++) sn[k] = __ldg(&g_csr_src[jn + k]);
        }
        __half2 hv[4];
#pragma unroll
        for (int k = 0; k < 4; k++)
            hv[k] = __ldcg((const __half2*)(g_h2 + (size_t)s[k] * D2) + lane);
        float e[4];
#pragma unroll
        for (int k = 0; k < 4; k++)
            e[k] = __expf(lrelu(__ldg(&g_as2[s[k]]) + adh));
#pragma unroll
        for (int k = 0; k < 4; k++) {
            den += e[k];
            float2 f = __half22float2(hv[k]);
            acc.x += e[k] * f.x;
            acc.y += e[k] * f.y;
        }
        j = jn;
        cur = nxt;
#pragma unroll
        for (int k = 0; k < 4; k++) s[k] = sn[k];
    }
    for (; j < end; j++) {
        int s0 = __ldg(&g_csr_src[j]);
        float e0 = __expf(lrelu(__ldg(&g_as2[s0]) + adh));
        den += e0;
        float2 f = __half22float2(__ldcg((const __half2*)(g_h2 + (size_t)s0 * D2) + lane));
        acc.x += e0 * f.x;
        acc.y += e0 * f.y;
    }
    float inv = 1.f / (den + 1e-16f);
    float2 bv = ((const float2*)b2)[lane];
    ((float2*)(out + (size_t)w * D2))[lane] =
        make_float2(acc.x * inv + bv.x, acc.y * inv + bv.y);
}

extern "C" void kernel_launch(void* const* d_in, const int* in_sizes, int n_in,
                              void* d_out, int out_size) {
    const float* x   = (const float*)d_in[0];
    const int*   ei  = (const int*)  d_in[1];
    const float* W1  = (const float*)d_in[2];
    const float* as1 = (const float*)d_in[3];
    const float* ad1 = (const float*)d_in[4];
    const float* b1  = (const float*)d_in[5];
    const float* W2  = (const float*)d_in[6];
    const float* as2 = (const float*)d_in[7];
    const float* ad2 = (const float*)d_in[8];
    const float* b2  = (const float*)d_in[9];
    float* out = (float*)d_out;

    static cudaStream_t s2 = nullptr;
    static cudaEvent_t evFork = nullptr, evJoin = nullptr;
    static cudaEvent_t evA[NCHP], evG[NCHP];
    if (!s2) {
        cudaStreamCreateWithFlags(&s2, cudaStreamNonBlocking);
        cudaEventCreateWithFlags(&evFork, cudaEventDisableTiming);
        cudaEventCreateWithFlags(&evJoin, cudaEventDisableTiming);
        for (int c = 0; c < NCHP; c++) {
            cudaEventCreateWithFlags(&evA[c], cudaEventDisableTiming);
            cudaEventCreateWithFlags(&evG[c], cudaEventDisableTiming);
        }
    }

    void *p_h1, *p_out1, *p_h2, *p_as1, *p_ad1, *p_as2, *p_ad2, *p_cnt;
    cudaGetSymbolAddress(&p_h1,   g_h1);
    cudaGetSymbolAddress(&p_out1, g_out1);
    cudaGetSymbolAddress(&p_h2,   g_h2);
    cudaGetSymbolAddress(&p_as1,  g_as1);
    cudaGetSymbolAddress(&p_ad1,  g_ad1);
    cudaGetSymbolAddress(&p_as2,  g_as2);
    cudaGetSymbolAddress(&p_ad2,  g_ad2);
    cudaGetSymbolAddress(&p_cnt,  g_cnt);

    // ---- fork: CSR build on s2, concurrent with GEMM1 ----
    cudaEventRecord(evFork, 0);
    cudaStreamWaitEvent(s2, evFork, 0);
    cudaMemsetAsync(p_cnt, 0, NN * sizeof(int), s2);
    hist<<<(NE / 4 + 255) / 256, 256, 0, s2>>>(ei);
    scan_fused<<<1, 1024, 0, s2>>>();
    scatter<<<(NE / 2 + NN + 255) / 256, 256, 0, s2>>>(ei);
    cudaEventRecord(evJoin, s2);

    // main stream: GEMM1 (fp16 HMMA) + fused scores
    {
        dim3 grid(D1 / 64, (NN + 127) / 128);
        gemm1_fused<<<grid, 256>>>(x, W1, (__half*)p_h1, as1, ad1,
                                   (float*)p_as1, (float*)p_ad1);
    }
    cudaStreamWaitEvent(0, evJoin, 0);

    // 4-chunk pipeline: aggr1(c) on main; gemm2(c) on s2 for c<NCHP-1,
    // gemm2(last) on main after its aggr1 chunk.
    for (int c = 0; c < NCHP; c++) {
        aggr1<<<(CHN + 7) / 8, 256>>>(b1, c * CHN, CHN);
        cudaEventRecord(evA[c], 0);
        if (c < NCHP - 1) {
            cudaStreamWaitEvent(s2, evA[c], 0);
            dim3 grid(1, (CHN + 127) / 128);
            gemm2_fused<<<grid, 256, 0, s2>>>((const __half*)p_out1, W2,
                                              (__half*)p_h2, as2, ad2,
                                              (float*)p_as2, (float*)p_ad2,
                                              c * CHN, CHN);
            cudaEventRecord(evG[c], s2);
        }
    }
    {
        dim3 grid(1, (CHN + 127) / 128);
        gemm2_fused<<<grid, 256>>>((const __half*)p_out1, W2, (__half*)p_h2,
                                   as2, ad2, (float*)p_as2, (float*)p_ad2,
                                   (NCHP - 1) * CHN, CHN);
    }
    for (int c = 0; c < NCHP - 1; c++)
        cudaStreamWaitEvent(0, evG[c], 0);
    aggr2<<<(NN + 7) / 8, 256>>>(out, b2);
}

// round 15
// speedup vs baseline: 1.0205x; 1.0205x over previous
#include <cuda_runtime.h>
#include <cuda_fp16.h>

#define NN   50000
#define NE   800000
#define ET   (NE + NN)
#define INC  128
#define HID  32
#define H1   8
#define D1   256
#define D2   64
#define NHALF 25000

__device__ __forceinline__ float lrelu(float v) { return v > 0.f ? v : 0.2f * v; }

// ---- scratch ----
__device__ __half   g_h1[(size_t)NN * D1];
__device__ __half   g_out1[(size_t)NN * D1];
__device__ float    g_as1[NN * H1];
__device__ float    g_ad1[NN * H1];
__device__ __half   g_h2[(size_t)NN * D2];
__device__ float    g_as2[NN];
__device__ float    g_ad2[NN];

// CSR
__device__ int g_cnt[NN];
__device__ int g_row[NN + 1];
__device__ int g_cur[NN];
__device__ int g_csr_src[ET];

// ============================================================
// CSR build
// ============================================================
__global__ void hist(const int* __restrict__ ei) {
    int i = blockIdx.x * blockDim.x + threadIdx.x;
    if (i * 4 >= NE) return;
    int4 d = *(const int4*)&ei[NE + i * 4];
    atomicAdd(&g_cnt[d.x], 1);
    atomicAdd(&g_cnt[d.y], 1);
    atomicAdd(&g_cnt[d.z], 1);
    atomicAdd(&g_cnt[d.w], 1);
}
__global__ void scan_fused() {
    __shared__ int wsum[32];
    __shared__ int s_carry;
    const int CH = 2048;
    int t = threadIdx.x, lane = t & 31, wid = t >> 5;
    if (t == 0) s_carry = 0;
    __syncthreads();
    for (int chunk = 0; chunk < (NN + CH - 1) / CH; chunk++) {
        int i0 = chunk * CH + 2 * t;
        int v0 = (i0     < NN) ? g_cnt[i0]     + 1 : 0;
        int v1 = (i0 + 1 < NN) ? g_cnt[i0 + 1] + 1 : 0;
        int p = v0 + v1;
        int x = p;
#pragma unroll
        for (int o = 1; o < 32; o <<= 1) {
            int y = __shfl_up_sync(0xffffffffu, x, o);
            if (lane >= o) x += y;
        }
        if (lane == 31) wsum[wid] = x;
        __syncthreads();
        if (wid == 0) {
            int w = wsum[lane];
#pragma unroll
            for (int o = 1; o < 32; o <<= 1) {
                int y = __shfl_up_sync(0xffffffffu, w, o);
                if (lane >= o) w += y;
            }
            wsum[lane] = w;
        }
        __syncthreads();
        int base = s_carry + (wid ? wsum[wid - 1] : 0);
        int excl = base + x - p;
        if (i0     < NN) { g_row[i0]     = excl;      g_cur[i0]     = excl; }
        if (i0 + 1 < NN) { g_row[i0 + 1] = excl + v0; g_cur[i0 + 1] = excl + v0; }
        __syncthreads();
        if (t == blockDim.x - 1) s_carry = base + x;
        __syncthreads();
    }
    if (t == 0) g_row[NN] = ET;
}
__global__ void scatter(const int* __restrict__ ei) {
    int i = blockIdx.x * blockDim.x + threadIdx.x;
    if (i < NE / 2) {
        int2 s = *(const int2*)&ei[2 * i];
        int2 d = *(const int2*)&ei[NE + 2 * i];
        int p0 = atomicAdd(&g_cur[d.x], 1); g_csr_src[p0] = s.x;
        int p1 = atomicAdd(&g_cur[d.y], 1); g_csr_src[p1] = s.y;
    } else {
        int e = i - NE / 2;
        if (e < NN) {
            int p = atomicAdd(&g_cur[e], 1);
            g_csr_src[p] = e;
        }
    }
}

// ============================================================
// fp16 MMA helper (m16n8k16)
// ============================================================
__device__ __forceinline__ void mma_f16(float c[4], const unsigned a[4],
                                        const unsigned b[2]) {
    asm volatile(
        "mma.sync.aligned.m16n8k16.row.col.f32.f16.f16.f32 "
        "{%0,%1,%2,%3}, {%4,%5,%6,%7}, {%8,%9}, {%0,%1,%2,%3};"
        : "+f"(c[0]), "+f"(c[1]), "+f"(c[2]), "+f"(c[3])
        : "r"(a[0]), "r"(a[1]), "r"(a[2]), "r"(a[3]), "r"(b[0]), "r"(b[1]));
}

#define ASTRIDE 20
#define BSTRIDE 72

// ============================================================
// GEMM1 fused (fp16 HMMA): h1 = x @ W1 (fp16 out) + att scores.
// Register-staged double buffering of k-tiles.
// ============================================================
__global__ void gemm1_fused(const float* __restrict__ A, const float* __restrict__ B,
                            __half* __restrict__ C,
                            const float* __restrict__ atts,
                            const float* __restrict__ attd,
                            float* __restrict__ as_, float* __restrict__ ad_) {
    const int BM = 128, BN = 64, BK = 32, M = NN, N = D1, K = INC;
    const int NT = K / BK;
    __shared__ __half2 As2[BM][ASTRIDE];
    __shared__ __half2 Bs2[BK / 2][BSTRIDE];

    int t = threadIdx.x, warp = t >> 5, lane = t & 31;
    int wm = warp >> 1, wn = warp & 1;
    int g = lane >> 2, t4 = lane & 3;
    int row0 = blockIdx.y * BM, col0 = blockIdx.x * BN;

    float acc[2][4][4] = {};

    float4 va[4];
    float bl[4], bh[4];

    {
#pragma unroll
        for (int i = 0; i < 4; i++) {
            int idx = t + i * 256;
            int r = idx >> 3, c4 = (idx & 7) * 4;
            int gr = row0 + r;
            va[i] = (gr < M) ? *(const float4*)&A[(size_t)gr * K + c4]
                             : make_float4(0.f, 0.f, 0.f, 0.f);
        }
#pragma unroll
        for (int i = 0; i < 4; i++) {
            int idx = t + i * 256;
            int kk = idx >> 6, n = idx & 63;
            bl[i] = B[(size_t)(2 * kk) * N + col0 + n];
            bh[i] = B[(size_t)(2 * kk + 1) * N + col0 + n];
        }
    }

    for (int it = 0; it < NT; it++) {
#pragma unroll
        for (int i = 0; i < 4; i++) {
            int idx = t + i * 256;
            int r = idx >> 3, c4 = (idx & 7) * 4;
            __half2 h0 = __floats2half2_rn(va[i].x, va[i].y);
            __half2 h1v = __floats2half2_rn(va[i].z, va[i].w);
            *(uint2*)&As2[r][c4 / 2] =
                make_uint2(*(unsigned*)&h0, *(unsigned*)&h1v);
        }
#pragma unroll
        for (int i = 0; i < 4; i++) {
            int idx = t + i * 256;
            int kk = idx >> 6, n = idx & 63;
            Bs2[kk][n] = __floats2half2_rn(bl[i], bh[i]);
        }
        __syncthreads();

        if (it + 1 < NT) {
            int kt = (it + 1) * BK;
#pragma unroll
            for (int i = 0; i < 4; i++) {
                int idx = t + i * 256;
                int r = idx >> 3, c4 = (idx & 7) * 4;
                int gr = row0 + r;
                va[i] = (gr < M) ? *(const float4*)&A[(size_t)gr * K + kt + c4]
                                 : make_float4(0.f, 0.f, 0.f, 0.f);
            }
#pragma unroll
            for (int i = 0; i < 4; i++) {
                int idx = t + i * 256;
                int kk = idx >> 6, n = idx & 63;
                bl[i] = B[(size_t)(kt + 2 * kk) * N + col0 + n];
                bh[i] = B[(size_t)(kt + 2 * kk + 1) * N + col0 + n];
            }
        }

#pragma unroll
        for (int k0 = 0; k0 < BK; k0 += 16) {
            int kk = k0 >> 1;
            unsigned a[2][4], b[4][2];
#pragma unroll
            for (int mi = 0; mi < 2; mi++) {
                int mb = wm * 32 + mi * 16;
                a[mi][0] = *(const unsigned*)&As2[mb + g][kk + t4];
                a[mi][1] = *(const unsigned*)&As2[mb + 8 + g][kk + t4];
                a[mi][2] = *(const unsigned*)&As2[mb + g][kk + 4 + t4];
                a[mi][3] = *(const unsigned*)&As2[mb + 8 + g][kk + 4 + t4];
            }
#pragma unroll
            for (int ni = 0; ni < 4; ni++) {
                int nb = wn * 32 + ni * 8;
                b[ni][0] = *(const unsigned*)&Bs2[kk + t4][nb + g];
                b[ni][1] = *(const unsigned*)&Bs2[kk + 4 + t4][nb + g];
            }
#pragma unroll
            for (int mi = 0; mi < 2; mi++)
#pragma unroll
                for (int ni = 0; ni < 4; ni++)
                    mma_f16(acc[mi][ni], a[mi], b[ni]);
        }
        __syncthreads();
    }

#pragma unroll
    for (int mi = 0; mi < 2; mi++)
#pragma unroll
        for (int ni = 0; ni < 4; ni++) {
            int col = col0 + wn * 32 + ni * 8 + t4 * 2;
            int r0 = row0 + wm * 32 + mi * 16 + g, r1 = r0 + 8;
            if (r0 < M)
                *(__half2*)&C[(size_t)r0 * N + col] =
                    __floats2half2_rn(acc[mi][ni][0], acc[mi][ni][1]);
            if (r1 < M)
                *(__half2*)&C[(size_t)r1 * N + col] =
                    __floats2half2_rn(acc[mi][ni][2], acc[mi][ni][3]);
        }

    int hidx = (col0 + wn * 32) >> 5;
    const float* aw = atts + hidx * HID;
    const float* dw = attd + hidx * HID;
#pragma unroll
    for (int mi = 0; mi < 2; mi++) {
        float ss0 = 0.f, dd0 = 0.f, ss1 = 0.f, dd1 = 0.f;
#pragma unroll
        for (int ni = 0; ni < 4; ni++) {
            int c = ni * 8 + t4 * 2;
            float a0 = aw[c], a1 = aw[c + 1];
            float d0 = dw[c], d1 = dw[c + 1];
            ss0 += acc[mi][ni][0] * a0 + acc[mi][ni][1] * a1;
            dd0 += acc[mi][ni][0] * d0 + acc[mi][ni][1] * d1;
            ss1 += acc[mi][ni][2] * a0 + acc[mi][ni][3] * a1;
            dd1 += acc[mi][ni][2] * d0 + acc[mi][ni][3] * d1;
        }
#pragma unroll
        for (int o = 1; o < 4; o <<= 1) {
            ss0 += __shfl_xor_sync(0xffffffffu, ss0, o);
            dd0 += __shfl_xor_sync(0xffffffffu, dd0, o);
            ss1 += __shfl_xor_sync(0xffffffffu, ss1, o);
            dd1 += __shfl_xor_sync(0xffffffffu, dd1, o);
        }
        if (t4 == 0) {
            int r0 = row0 + wm * 32 + mi * 16 + g, r1 = r0 + 8;
            if (r0 < M) { as_[r0 * H1 + hidx] = ss0; ad_[r0 * H1 + hidx] = dd0; }
            if (r1 < M) { as_[r1 * H1 + hidx] = ss1; ad_[r1 * H1 + hidx] = dd1; }
        }
    }
}

// ============================================================
// GEMM2 fused (fp16 HMMA), row-range parametrized (simple loop).
// ============================================================
__global__ void gemm2_fused(const __half* __restrict__ A, const float* __restrict__ B,
                            __half* __restrict__ C,
                            const float* __restrict__ atts,
                            const float* __restrict__ attd,
                            float* __restrict__ as_, float* __restrict__ ad_,
                            int row_base, int nrows) {
    const int BM = 128, BN = 64, BK = 32, N = D2, K = D1;
    const int Mlim = row_base + nrows;
    __shared__ __half2 As2[BM][ASTRIDE];
    __shared__ __half2 Bs2[BK / 2][BSTRIDE];
    __shared__ float sS[BM][2], sD[BM][2];

    int t = threadIdx.x, warp = t >> 5, lane = t & 31;
    int wm = warp >> 1, wn = warp & 1;
    int g = lane >> 2, t4 = lane & 3;
    int row0 = row_base + blockIdx.y * BM;

    float acc[2][4][4] = {};

    for (int kt = 0; kt < K; kt += BK) {
#pragma unroll
        for (int i = 0; i < 2; i++) {
            int idx = t + i * 256;
            int r = idx >> 2, c8 = (idx & 3) * 8;
            int gr = row0 + r;
            uint4 raw = (gr < Mlim) ? *(const uint4*)&A[(size_t)gr * K + kt + c8]
                                    : make_uint4(0, 0, 0, 0);
            *(uint2*)&As2[r][c8 / 2]     = make_uint2(raw.x, raw.y);
            *(uint2*)&As2[r][c8 / 2 + 2] = make_uint2(raw.z, raw.w);
        }
#pragma unroll
        for (int i = 0; i < 4; i++) {
            int idx = t + i * 256;
            int kk = idx >> 6, n = idx & 63;
            float lo = B[(size_t)(kt + 2 * kk) * N + n];
            float hi = B[(size_t)(kt + 2 * kk + 1) * N + n];
            Bs2[kk][n] = __floats2half2_rn(lo, hi);
        }
        __syncthreads();
#pragma unroll
        for (int k0 = 0; k0 < BK; k0 += 16) {
            int kk = k0 >> 1;
            unsigned a[2][4], b[4][2];
#pragma unroll
            for (int mi = 0; mi < 2; mi++) {
                int mb = wm * 32 + mi * 16;
                a[mi][0] = *(const unsigned*)&As2[mb + g][kk + t4];
                a[mi][1] = *(const unsigned*)&As2[mb + 8 + g][kk + t4];
                a[mi][2] = *(const unsigned*)&As2[mb + g][kk + 4 + t4];
                a[mi][3] = *(const unsigned*)&As2[mb + 8 + g][kk + 4 + t4];
            }
#pragma unroll
            for (int ni = 0; ni < 4; ni++) {
                int nb = wn * 32 + ni * 8;
                b[ni][0] = *(const unsigned*)&Bs2[kk + t4][nb + g];
                b[ni][1] = *(const unsigned*)&Bs2[kk + 4 + t4][nb + g];
            }
#pragma unroll
            for (int mi = 0; mi < 2; mi++)
#pragma unroll
                for (int ni = 0; ni < 4; ni++)
                    mma_f16(acc[mi][ni], a[mi], b[ni]);
        }
        __syncthreads();
    }

#pragma unroll
    for (int mi = 0; mi < 2; mi++)
#pragma unroll
        for (int ni = 0; ni < 4; ni++) {
            int col = wn * 32 + ni * 8 + t4 * 2;
            int r0 = row0 + wm * 32 + mi * 16 + g, r1 = r0 + 8;
            if (r0 < Mlim)
                *(__half2*)&C[(size_t)r0 * N + col] =
                    __floats2half2_rn(acc[mi][ni][0], acc[mi][ni][1]);
            if (r1 < Mlim)
                *(__half2*)&C[(size_t)r1 * N + col] =
                    __floats2half2_rn(acc[mi][ni][2], acc[mi][ni][3]);
        }

#pragma unroll
    for (int mi = 0; mi < 2; mi++) {
        float ss0 = 0.f, dd0 = 0.f, ss1 = 0.f, dd1 = 0.f;
#pragma unroll
        for (int ni = 0; ni < 4; ni++) {
            int c = wn * 32 + ni * 8 + t4 * 2;
            float a0 = atts[c], a1 = atts[c + 1];
            float d0 = attd[c], d1 = attd[c + 1];
            ss0 += acc[mi][ni][0] * a0 + acc[mi][ni][1] * a1;
            dd0 += acc[mi][ni][0] * d0 + acc[mi][ni][1] * d1;
            ss1 += acc[mi][ni][2] * a0 + acc[mi][ni][3] * a1;
            dd1 += acc[mi][ni][2] * d0 + acc[mi][ni][3] * d1;
        }
#pragma unroll
        for (int o = 1; o < 4; o <<= 1) {
            ss0 += __shfl_xor_sync(0xffffffffu, ss0, o);
            dd0 += __shfl_xor_sync(0xffffffffu, dd0, o);
            ss1 += __shfl_xor_sync(0xffffffffu, ss1, o);
            dd1 += __shfl_xor_sync(0xffffffffu, dd1, o);
        }
        if (t4 == 0) {
            int lr0 = wm * 32 + mi * 16 + g, lr1 = lr0 + 8;
            sS[lr0][wn] = ss0; sD[lr0][wn] = dd0;
            sS[lr1][wn] = ss1; sD[lr1][wn] = dd1;
        }
    }
    __syncthreads();
    if (t < BM) {
        int gr = row0 + t;
        if (gr < Mlim) {
            as_[gr] = sS[t][0] + sS[t][1];
            ad_[gr] = sD[t][0] + sD[t][1];
        }
    }
}

// ============================================================
// layer1 aggregation: warp per node, own-head exp, half2 pair
// accumulation. Index AND score prefetch one batch ahead.
// ============================================================
__global__ void aggr1(const float* __restrict__ b1, int node_base, int nnodes) {
    int gw   = (blockIdx.x * blockDim.x + threadIdx.x) >> 5;
    int lane = threadIdx.x & 31;
    if (gw >= nnodes) return;
    int node = node_base + gw;
    int head = lane >> 2;

    float adh = g_ad1[node * H1 + head];
    int beg = g_row[node], end = g_row[node + 1];

    float den = 0.f;
    float acc[8] = {};
    const __half* hbase = g_h1 + lane * 8;

    int j = beg;
    int s[4];
    float a[4];
    bool cur = (j + 3 < end);
    if (cur) {
#pragma unroll
        for (int k = 0; k < 4; k++) s[k] = __ldg(&g_csr_src[j + k]);
#pragma unroll
        for (int k = 0; k < 4; k++) a[k] = __ldg(&g_as1[s[k] * H1 + head]);
    }
    while (cur) {
        // issue current rows first (longest latency)
        uint4 r[4];
#pragma unroll
        for (int k = 0; k < 4; k++)
            r[k] = __ldg((const uint4*)(hbase + (size_t)s[k] * D1));
        // prefetch next indices + scores
        int jn = j + 4;
        bool nxt = (jn + 3 < end);
        int sn[4];
        float an[4];
        if (nxt) {
#pragma unroll
            for (int k = 0; k < 4; k++) sn[k] = __ldg(&g_csr_src[jn + k]);
#pragma unroll
            for (int k = 0; k < 4; k++) an[k] = __ldg(&g_as1[sn[k] * H1 + head]);
        }
        // consume current (scores already resident)
        float e[4];
#pragma unroll
        for (int k = 0; k < 4; k++)
            e[k] = __expf(lrelu(a[k] + adh));
        den += (e[0] + e[1]) + (e[2] + e[3]);
        __half2 eh[4];
#pragma unroll
        for (int k = 0; k < 4; k++)
            eh[k] = __float2half2_rn(e[k]);
        const __half2* p0 = (const __half2*)&r[0];
        const __half2* p1 = (const __half2*)&r[1];
        const __half2* p2 = (const __half2*)&r[2];
        const __half2* p3 = (const __half2*)&r[3];
#pragma unroll
        for (int q = 0; q < 4; q++) {
            __half2 t01 = __hfma2(p1[q], eh[1], __hmul2(p0[q], eh[0]));
            __half2 t23 = __hfma2(p3[q], eh[3], __hmul2(p2[q], eh[2]));
            float2 f01 = __half22float2(t01);
            float2 f23 = __half22float2(t23);
            acc[2 * q]     += f01.x + f23.x;
            acc[2 * q + 1] += f01.y + f23.y;
        }
        j = jn;
        cur = nxt;
#pragma unroll
        for (int k = 0; k < 4; k++) { s[k] = sn[k]; a[k] = an[k]; }
    }
    for (; j < end; j++) {
        int s0 = __ldg(&g_csr_src[j]);
        float e0 = __expf(lrelu(__ldg(&g_as1[s0 * H1 + head]) + adh));
        den += e0;
        uint4 r0 = __ldg((const uint4*)(hbase + (size_t)s0 * D1));
        const __half2* p = (const __half2*)&r0;
#pragma unroll
        for (int q = 0; q < 4; q++) {
            float2 f = __half22float2(p[q]);
            acc[2 * q]     += e0 * f.x;
            acc[2 * q + 1] += e0 * f.y;
        }
    }

    float inv = 1.f / (den + 1e-16f);
    const float* bb = b1 + lane * 8;
    __half2 o[4];
#pragma unroll
    for (int q = 0; q < 4; q++) {
        float f0 = fmaxf(acc[2 * q]     * inv + bb[2 * q],     0.f);
        float f1 = fmaxf(acc[2 * q + 1] * inv + bb[2 * q + 1], 0.f);
        o[q] = __floats2half2_rn(f0, f1);
    }
    *(uint4*)(g_out1 + (size_t)node * D1 + lane * 8) = *(uint4*)o;
}

// ---- layer2 aggregation: warp per node, batch-8 (1 reg/row per lane),
// index + score prefetch one batch ahead ----
__global__ void aggr2(float* __restrict__ out, const float* __restrict__ b2) {
    int w    = (blockIdx.x * blockDim.x + threadIdx.x) >> 5;
    int lane = threadIdx.x & 31;
    if (w >= NN) return;
    float adh = g_ad2[w];
    int beg = g_row[w], end = g_row[w + 1];

    float den = 0.f;
    float2 acc = {0.f, 0.f};
    int j = beg;
    int s[8];
    float a[8];
    bool cur = (j + 7 < end);
    if (cur) {
#pragma unroll
        for (int k = 0; k < 8; k++) s[k] = __ldg(&g_csr_src[j + k]);
#pragma unroll
        for (int k = 0; k < 8; k++) a[k] = __ldg(&g_as2[s[k]]);
    }
    while (cur) {
        __half2 hv[8];
#pragma unroll
        for (int k = 0; k < 8; k++)
            hv[k] = __ldg((const __half2*)(g_h2 + (size_t)s[k] * D2) + lane);
        int jn = j + 8;
        bool nxt = (jn + 7 < end);
        int sn[8];
        float an[8];
        if (nxt) {
#pragma unroll
            for (int k = 0; k < 8; k++) sn[k] = __ldg(&g_csr_src[jn + k]);
#pragma unroll
            for (int k = 0; k < 8; k++) an[k] = __ldg(&g_as2[sn[k]]);
        }
#pragma unroll
        for (int k = 0; k < 8; k++) {
            float e = __expf(lrelu(a[k] + adh));
            den += e;
            float2 f = __half22float2(hv[k]);
            acc.x += e * f.x;
            acc.y += e * f.y;
        }
        j = jn;
        cur = nxt;
#pragma unroll
        for (int k = 0; k < 8; k++) { s[k] = sn[k]; a[k] = an[k]; }
    }
    for (; j < end; j++) {
        int s0 = __ldg(&g_csr_src[j]);
        float e0 = __expf(lrelu(__ldg(&g_as2[s0]) + adh));
        den += e0;
        float2 f = __half22float2(__ldg((const __half2*)(g_h2 + (size_t)s0 * D2) + lane));
        acc.x += e0 * f.x;
        acc.y += e0 * f.y;
    }
    float inv = 1.f / (den + 1e-16f);
    float2 bv = ((const float2*)b2)[lane];
    ((float2*)(out + (size_t)w * D2))[lane] =
        make_float2(acc.x * inv + bv.x, acc.y * inv + bv.y);
}

extern "C" void kernel_launch(void* const* d_in, const int* in_sizes, int n_in,
                              void* d_out, int out_size) {
    const float* x   = (const float*)d_in[0];
    const int*   ei  = (const int*)  d_in[1];
    const float* W1  = (const float*)d_in[2];
    const float* as1 = (const float*)d_in[3];
    const float* ad1 = (const float*)d_in[4];
    const float* b1  = (const float*)d_in[5];
    const float* W2  = (const float*)d_in[6];
    const float* as2 = (const float*)d_in[7];
    const float* ad2 = (const float*)d_in[8];
    const float* b2  = (const float*)d_in[9];
    float* out = (float*)d_out;

    static cudaStream_t s2 = nullptr;
    static cudaEvent_t evFork = nullptr, evJoin = nullptr, evA0 = nullptr, evG0 = nullptr;
    if (!s2) {
        cudaStreamCreateWithFlags(&s2, cudaStreamNonBlocking);
        cudaEventCreateWithFlags(&evFork, cudaEventDisableTiming);
        cudaEventCreateWithFlags(&evJoin, cudaEventDisableTiming);
        cudaEventCreateWithFlags(&evA0,   cudaEventDisableTiming);
        cudaEventCreateWithFlags(&evG0,   cudaEventDisableTiming);
    }

    void *p_h1, *p_out1, *p_h2, *p_as1, *p_ad1, *p_as2, *p_ad2, *p_cnt;
    cudaGetSymbolAddress(&p_h1,   g_h1);
    cudaGetSymbolAddress(&p_out1, g_out1);
    cudaGetSymbolAddress(&p_h2,   g_h2);
    cudaGetSymbolAddress(&p_as1,  g_as1);
    cudaGetSymbolAddress(&p_ad1,  g_ad1);
    cudaGetSymbolAddress(&p_as2,  g_as2);
    cudaGetSymbolAddress(&p_ad2,  g_ad2);
    cudaGetSymbolAddress(&p_cnt,  g_cnt);

    // ---- fork: CSR build on s2, concurrent with GEMM1 ----
    cudaEventRecord(evFork, 0);
    cudaStreamWaitEvent(s2, evFork, 0);
    cudaMemsetAsync(p_cnt, 0, NN * sizeof(int), s2);
    hist<<<(NE / 4 + 255) / 256, 256, 0, s2>>>(ei);
    scan_fused<<<1, 1024, 0, s2>>>();
    scatter<<<(NE / 2 + NN + 255) / 256, 256, 0, s2>>>(ei);
    cudaEventRecord(evJoin, s2);

    // main stream: GEMM1 (fp16 HMMA) + fused scores
    {
        dim3 grid(D1 / 64, (NN + 127) / 128);
        gemm1_fused<<<grid, 256>>>(x, W1, (__half*)p_h1, as1, ad1,
                                   (float*)p_as1, (float*)p_ad1);
    }
    cudaStreamWaitEvent(0, evJoin, 0);

    // pipelined halves: aggr1(H0) -> {gemm2(H0) on s2 || aggr1(H1)} -> gemm2(H1)
    aggr1<<<(NHALF + 7) / 8, 256>>>(b1, 0, NHALF);
    cudaEventRecord(evA0, 0);

    cudaStreamWaitEvent(s2, evA0, 0);
    {
        dim3 grid(1, (NHALF + 127) / 128);
        gemm2_fused<<<grid, 256, 0, s2>>>((const __half*)p_out1, W2, (__half*)p_h2,
                                          as2, ad2, (float*)p_as2, (float*)p_ad2,
                                          0, NHALF);
    }
    cudaEventRecord(evG0, s2);

    aggr1<<<(NN - NHALF + 7) / 8, 256>>>(b1, NHALF, NN - NHALF);
    {
        dim3 grid(1, (NN - NHALF + 127) / 128);
        gemm2_fused<<<grid, 256>>>((const __half*)p_out1, W2, (__half*)p_h2,
                                   as2, ad2, (float*)p_as2, (float*)p_ad2,
                                   NHALF, NN - NHALF);
    }
    cudaStreamWaitEvent(0, evG0, 0);
    aggr2<<<(NN + 7) / 8, 256>>>(out, b2);
}

// round 16
// speedup vs baseline: 1.0631x; 1.0418x over previous
#include <cuda_runtime.h>
#include <cuda_fp16.h>

#define NN   50000
#define NE   800000
#define ET   (NE + NN)
#define INC  128
#define HID  32
#define H1   8
#define D1   256
#define D2   64
#define NH0  37500            // uneven pipeline halves
#define NH1  (NN - NH0)       // 12500

__device__ __forceinline__ float lrelu(float v) { return v > 0.f ? v : 0.2f * v; }

// ---- scratch ----
__device__ __half   g_h1[(size_t)NN * D1];
__device__ __half   g_out1[(size_t)NN * D1];
__device__ float    g_as1[NN * H1];
__device__ float    g_ad1[NN * H1];
__device__ __half   g_h2[(size_t)NN * D2];
__device__ float    g_as2[NN];
__device__ float    g_ad2[NN];

// CSR
__device__ int g_cnt[NN];
__device__ int g_row[NN + 1];
__device__ int g_cur[NN];
__device__ int g_csr_src[ET];

// ============================================================
// CSR build
// ============================================================
__global__ void hist(const int* __restrict__ ei) {
    int i = blockIdx.x * blockDim.x + threadIdx.x;
    if (i * 4 >= NE) return;
    int4 d = *(const int4*)&ei[NE + i * 4];
    atomicAdd(&g_cnt[d.x], 1);
    atomicAdd(&g_cnt[d.y], 1);
    atomicAdd(&g_cnt[d.z], 1);
    atomicAdd(&g_cnt[d.w], 1);
}
__global__ void scan_fused() {
    __shared__ int wsum[32];
    __shared__ int s_carry;
    const int CH = 2048;
    int t = threadIdx.x, lane = t & 31, wid = t >> 5;
    if (t == 0) s_carry = 0;
    __syncthreads();
    for (int chunk = 0; chunk < (NN + CH - 1) / CH; chunk++) {
        int i0 = chunk * CH + 2 * t;
        int v0 = (i0     < NN) ? g_cnt[i0]     + 1 : 0;
        int v1 = (i0 + 1 < NN) ? g_cnt[i0 + 1] + 1 : 0;
        int p = v0 + v1;
        int x = p;
#pragma unroll
        for (int o = 1; o < 32; o <<= 1) {
            int y = __shfl_up_sync(0xffffffffu, x, o);
            if (lane >= o) x += y;
        }
        if (lane == 31) wsum[wid] = x;
        __syncthreads();
        if (wid == 0) {
            int w = wsum[lane];
#pragma unroll
            for (int o = 1; o < 32; o <<= 1) {
                int y = __shfl_up_sync(0xffffffffu, w, o);
                if (lane >= o) w += y;
            }
            wsum[lane] = w;
        }
        __syncthreads();
        int base = s_carry + (wid ? wsum[wid - 1] : 0);
        int excl = base + x - p;
        if (i0     < NN) { g_row[i0]     = excl;      g_cur[i0]     = excl; }
        if (i0 + 1 < NN) { g_row[i0 + 1] = excl + v0; g_cur[i0 + 1] = excl + v0; }
        __syncthreads();
        if (t == blockDim.x - 1) s_carry = base + x;
        __syncthreads();
    }
    if (t == 0) g_row[NN] = ET;
}
__global__ void scatter(const int* __restrict__ ei) {
    int i = blockIdx.x * blockDim.x + threadIdx.x;
    if (i < NE / 2) {
        int2 s = *(const int2*)&ei[2 * i];
        int2 d = *(const int2*)&ei[NE + 2 * i];
        int p0 = atomicAdd(&g_cur[d.x], 1); g_csr_src[p0] = s.x;
        int p1 = atomicAdd(&g_cur[d.y], 1); g_csr_src[p1] = s.y;
    } else {
        int e = i - NE / 2;
        if (e < NN) {
            int p = atomicAdd(&g_cur[e], 1);
            g_csr_src[p] = e;
        }
    }
}

// ============================================================
// fp16 MMA helper (m16n8k16)
// ============================================================
__device__ __forceinline__ void mma_f16(float c[4], const unsigned a[4],
                                        const unsigned b[2]) {
    asm volatile(
        "mma.sync.aligned.m16n8k16.row.col.f32.f16.f16.f32 "
        "{%0,%1,%2,%3}, {%4,%5,%6,%7}, {%8,%9}, {%0,%1,%2,%3};"
        : "+f"(c[0]), "+f"(c[1]), "+f"(c[2]), "+f"(c[3])
        : "r"(a[0]), "r"(a[1]), "r"(a[2]), "r"(a[3]), "r"(b[0]), "r"(b[1]));
}

#define ASTRIDE 20
#define BSTRIDE 72

// ============================================================
// GEMM1 fused (fp16 HMMA): h1 = x @ W1 (fp16 out) + att scores.
// Register-staged double buffering of k-tiles.
// ============================================================
__global__ void gemm1_fused(const float* __restrict__ A, const float* __restrict__ B,
                            __half* __restrict__ C,
                            const float* __restrict__ atts,
                            const float* __restrict__ attd,
                            float* __restrict__ as_, float* __restrict__ ad_) {
    const int BM = 128, BN = 64, BK = 32, M = NN, N = D1, K = INC;
    const int NT = K / BK;
    __shared__ __half2 As2[BM][ASTRIDE];
    __shared__ __half2 Bs2[BK / 2][BSTRIDE];

    int t = threadIdx.x, warp = t >> 5, lane = t & 31;
    int wm = warp >> 1, wn = warp & 1;
    int g = lane >> 2, t4 = lane & 3;
    int row0 = blockIdx.y * BM, col0 = blockIdx.x * BN;

    float acc[2][4][4] = {};

    float4 va[4];
    float bl[4], bh[4];

    {
#pragma unroll
        for (int i = 0; i < 4; i++) {
            int idx = t + i * 256;
            int r = idx >> 3, c4 = (idx & 7) * 4;
            int gr = row0 + r;
            va[i] = (gr < M) ? *(const float4*)&A[(size_t)gr * K + c4]
                             : make_float4(0.f, 0.f, 0.f, 0.f);
        }
#pragma unroll
        for (int i = 0; i < 4; i++) {
            int idx = t + i * 256;
            int kk = idx >> 6, n = idx & 63;
            bl[i] = B[(size_t)(2 * kk) * N + col0 + n];
            bh[i] = B[(size_t)(2 * kk + 1) * N + col0 + n];
        }
    }

    for (int it = 0; it < NT; it++) {
#pragma unroll
        for (int i = 0; i < 4; i++) {
            int idx = t + i * 256;
            int r = idx >> 3, c4 = (idx & 7) * 4;
            __half2 h0 = __floats2half2_rn(va[i].x, va[i].y);
            __half2 h1v = __floats2half2_rn(va[i].z, va[i].w);
            *(uint2*)&As2[r][c4 / 2] =
                make_uint2(*(unsigned*)&h0, *(unsigned*)&h1v);
        }
#pragma unroll
        for (int i = 0; i < 4; i++) {
            int idx = t + i * 256;
            int kk = idx >> 6, n = idx & 63;
            Bs2[kk][n] = __floats2half2_rn(bl[i], bh[i]);
        }
        __syncthreads();

        if (it + 1 < NT) {
            int kt = (it + 1) * BK;
#pragma unroll
            for (int i = 0; i < 4; i++) {
                int idx = t + i * 256;
                int r = idx >> 3, c4 = (idx & 7) * 4;
                int gr = row0 + r;
                va[i] = (gr < M) ? *(const float4*)&A[(size_t)gr * K + kt + c4]
                                 : make_float4(0.f, 0.f, 0.f, 0.f);
            }
#pragma unroll
            for (int i = 0; i < 4; i++) {
                int idx = t + i * 256;
                int kk = idx >> 6, n = idx & 63;
                bl[i] = B[(size_t)(kt + 2 * kk) * N + col0 + n];
                bh[i] = B[(size_t)(kt + 2 * kk + 1) * N + col0 + n];
            }
        }

#pragma unroll
        for (int k0 = 0; k0 < BK; k0 += 16) {
            int kk = k0 >> 1;
            unsigned a[2][4], b[4][2];
#pragma unroll
            for (int mi = 0; mi < 2; mi++) {
                int mb = wm * 32 + mi * 16;
                a[mi][0] = *(const unsigned*)&As2[mb + g][kk + t4];
                a[mi][1] = *(const unsigned*)&As2[mb + 8 + g][kk + t4];
                a[mi][2] = *(const unsigned*)&As2[mb + g][kk + 4 + t4];
                a[mi][3] = *(const unsigned*)&As2[mb + 8 + g][kk + 4 + t4];
            }
#pragma unroll
            for (int ni = 0; ni < 4; ni++) {
                int nb = wn * 32 + ni * 8;
                b[ni][0] = *(const unsigned*)&Bs2[kk + t4][nb + g];
                b[ni][1] = *(const unsigned*)&Bs2[kk + 4 + t4][nb + g];
            }
#pragma unroll
            for (int mi = 0; mi < 2; mi++)
#pragma unroll
                for (int ni = 0; ni < 4; ni++)
                    mma_f16(acc[mi][ni], a[mi], b[ni]);
        }
        __syncthreads();
    }

#pragma unroll
    for (int mi = 0; mi < 2; mi++)
#pragma unroll
        for (int ni = 0; ni < 4; ni++) {
            int col = col0 + wn * 32 + ni * 8 + t4 * 2;
            int r0 = row0 + wm * 32 + mi * 16 + g, r1 = r0 + 8;
            if (r0 < M)
                *(__half2*)&C[(size_t)r0 * N + col] =
                    __floats2half2_rn(acc[mi][ni][0], acc[mi][ni][1]);
            if (r1 < M)
                *(__half2*)&C[(size_t)r1 * N + col] =
                    __floats2half2_rn(acc[mi][ni][2], acc[mi][ni][3]);
        }

    int hidx = (col0 + wn * 32) >> 5;
    const float* aw = atts + hidx * HID;
    const float* dw = attd + hidx * HID;
#pragma unroll
    for (int mi = 0; mi < 2; mi++) {
        float ss0 = 0.f, dd0 = 0.f, ss1 = 0.f, dd1 = 0.f;
#pragma unroll
        for (int ni = 0; ni < 4; ni++) {
            int c = ni * 8 + t4 * 2;
            float a0 = aw[c], a1 = aw[c + 1];
            float d0 = dw[c], d1 = dw[c + 1];
            ss0 += acc[mi][ni][0] * a0 + acc[mi][ni][1] * a1;
            dd0 += acc[mi][ni][0] * d0 + acc[mi][ni][1] * d1;
            ss1 += acc[mi][ni][2] * a0 + acc[mi][ni][3] * a1;
            dd1 += acc[mi][ni][2] * d0 + acc[mi][ni][3] * d1;
        }
#pragma unroll
        for (int o = 1; o < 4; o <<= 1) {
            ss0 += __shfl_xor_sync(0xffffffffu, ss0, o);
            dd0 += __shfl_xor_sync(0xffffffffu, dd0, o);
            ss1 += __shfl_xor_sync(0xffffffffu, ss1, o);
            dd1 += __shfl_xor_sync(0xffffffffu, dd1, o);
        }
        if (t4 == 0) {
            int r0 = row0 + wm * 32 + mi * 16 + g, r1 = r0 + 8;
            if (r0 < M) { as_[r0 * H1 + hidx] = ss0; ad_[r0 * H1 + hidx] = dd0; }
            if (r1 < M) { as_[r1 * H1 + hidx] = ss1; ad_[r1 * H1 + hidx] = dd1; }
        }
    }
}

// ============================================================
// GEMM2 fused (fp16 HMMA), row-range parametrized (simple loop).
// ============================================================
__global__ void gemm2_fused(const __half* __restrict__ A, const float* __restrict__ B,
                            __half* __restrict__ C,
                            const float* __restrict__ atts,
                            const float* __restrict__ attd,
                            float* __restrict__ as_, float* __restrict__ ad_,
                            int row_base, int nrows) {
    const int BM = 128, BN = 64, BK = 32, N = D2, K = D1;
    const int Mlim = row_base + nrows;
    __shared__ __half2 As2[BM][ASTRIDE];
    __shared__ __half2 Bs2[BK / 2][BSTRIDE];
    __shared__ float sS[BM][2], sD[BM][2];

    int t = threadIdx.x, warp = t >> 5, lane = t & 31;
    int wm = warp >> 1, wn = warp & 1;
    int g = lane >> 2, t4 = lane & 3;
    int row0 = row_base + blockIdx.y * BM;

    float acc[2][4][4] = {};

    for (int kt = 0; kt < K; kt += BK) {
#pragma unroll
        for (int i = 0; i < 2; i++) {
            int idx = t + i * 256;
            int r = idx >> 2, c8 = (idx & 3) * 8;
            int gr = row0 + r;
            uint4 raw = (gr < Mlim) ? *(const uint4*)&A[(size_t)gr * K + kt + c8]
                                    : make_uint4(0, 0, 0, 0);
            *(uint2*)&As2[r][c8 / 2]     = make_uint2(raw.x, raw.y);
            *(uint2*)&As2[r][c8 / 2 + 2] = make_uint2(raw.z, raw.w);
        }
#pragma unroll
        for (int i = 0; i < 4; i++) {
            int idx = t + i * 256;
            int kk = idx >> 6, n = idx & 63;
            float lo = B[(size_t)(kt + 2 * kk) * N + n];
            float hi = B[(size_t)(kt + 2 * kk + 1) * N + n];
            Bs2[kk][n] = __floats2half2_rn(lo, hi);
        }
        __syncthreads();
#pragma unroll
        for (int k0 = 0; k0 < BK; k0 += 16) {
            int kk = k0 >> 1;
            unsigned a[2][4], b[4][2];
#pragma unroll
            for (int mi = 0; mi < 2; mi++) {
                int mb = wm * 32 + mi * 16;
                a[mi][0] = *(const unsigned*)&As2[mb + g][kk + t4];
                a[mi][1] = *(const unsigned*)&As2[mb + 8 + g][kk + t4];
                a[mi][2] = *(const unsigned*)&As2[mb + g][kk + 4 + t4];
                a[mi][3] = *(const unsigned*)&As2[mb + 8 + g][kk + 4 + t4];
            }
#pragma unroll
            for (int ni = 0; ni < 4; ni++) {
                int nb = wn * 32 + ni * 8;
                b[ni][0] = *(const unsigned*)&Bs2[kk + t4][nb + g];
                b[ni][1] = *(const unsigned*)&Bs2[kk + 4 + t4][nb + g];
            }
#pragma unroll
            for (int mi = 0; mi < 2; mi++)
#pragma unroll
                for (int ni = 0; ni < 4; ni++)
                    mma_f16(acc[mi][ni], a[mi], b[ni]);
        }
        __syncthreads();
    }

#pragma unroll
    for (int mi = 0; mi < 2; mi++)
#pragma unroll
        for (int ni = 0; ni < 4; ni++) {
            int col = wn * 32 + ni * 8 + t4 * 2;
            int r0 = row0 + wm * 32 + mi * 16 + g, r1 = r0 + 8;
            if (r0 < Mlim)
                *(__half2*)&C[(size_t)r0 * N + col] =
                    __floats2half2_rn(acc[mi][ni][0], acc[mi][ni][1]);
            if (r1 < Mlim)
                *(__half2*)&C[(size_t)r1 * N + col] =
                    __floats2half2_rn(acc[mi][ni][2], acc[mi][ni][3]);
        }

#pragma unroll
    for (int mi = 0; mi < 2; mi++) {
        float ss0 = 0.f, dd0 = 0.f, ss1 = 0.f, dd1 = 0.f;
#pragma unroll
        for (int ni = 0; ni < 4; ni++) {
            int c = wn * 32 + ni * 8 + t4 * 2;
            float a0 = atts[c], a1 = atts[c + 1];
            float d0 = attd[c], d1 = attd[c + 1];
            ss0 += acc[mi][ni][0] * a0 + acc[mi][ni][1] * a1;
            dd0 += acc[mi][ni][0] * d0 + acc[mi][ni][1] * d1;
            ss1 += acc[mi][ni][2] * a0 + acc[mi][ni][3] * a1;
            dd1 += acc[mi][ni][2] * d0 + acc[mi][ni][3] * d1;
        }
#pragma unroll
        for (int o = 1; o < 4; o <<= 1) {
            ss0 += __shfl_xor_sync(0xffffffffu, ss0, o);
            dd0 += __shfl_xor_sync(0xffffffffu, dd0, o);
            ss1 += __shfl_xor_sync(0xffffffffu, ss1, o);
            dd1 += __shfl_xor_sync(0xffffffffu, dd1, o);
        }
        if (t4 == 0) {
            int lr0 = wm * 32 + mi * 16 + g, lr1 = lr0 + 8;
            sS[lr0][wn] = ss0; sD[lr0][wn] = dd0;
            sS[lr1][wn] = ss1; sD[lr1][wn] = dd1;
        }
    }
    __syncthreads();
    if (t < BM) {
        int gr = row0 + t;
        if (gr < Mlim) {
            as_[gr] = sS[t][0] + sS[t][1];
            ad_[gr] = sD[t][0] + sD[t][1];
        }
    }
}

// ============================================================
// layer1 aggregation: warp per node, own-head exp, half2 pair
// accumulation (exact R13 shape).
// ============================================================
__global__ void aggr1(const float* __restrict__ b1, int node_base, int nnodes) {
    int gw   = (blockIdx.x * blockDim.x + threadIdx.x) >> 5;
    int lane = threadIdx.x & 31;
    if (gw >= nnodes) return;
    int node = node_base + gw;
    int head = lane >> 2;

    float adh = g_ad1[node * H1 + head];
    int beg = g_row[node], end = g_row[node + 1];

    float den = 0.f;
    float acc[8] = {};
    const __half* hbase = g_h1 + lane * 8;

    int j = beg;
    int s[4];
    bool cur = (j + 3 < end);
    if (cur) {
#pragma unroll
        for (int k = 0; k < 4; k++) s[k] = __ldg(&g_csr_src[j + k]);
    }
    while (cur) {
        int jn = j + 4;
        bool nxt = (jn + 3 < end);
        int sn[4];
        if (nxt) {
#pragma unroll
            for (int k = 0; k < 4; k++) sn[k] = __ldg(&g_csr_src[jn + k]);
        }
        uint4 r[4];
#pragma unroll
        for (int k = 0; k < 4; k++)
            r[k] = __ldg((const uint4*)(hbase + (size_t)s[k] * D1));
        float e[4];
#pragma unroll
        for (int k = 0; k < 4; k++)
            e[k] = __expf(lrelu(__ldg(&g_as1[s[k] * H1 + head]) + adh));
        den += (e[0] + e[1]) + (e[2] + e[3]);
        __half2 eh[4];
#pragma unroll
        for (int k = 0; k < 4; k++)
            eh[k] = __float2half2_rn(e[k]);
        const __half2* p0 = (const __half2*)&r[0];
        const __half2* p1 = (const __half2*)&r[1];
        const __half2* p2 = (const __half2*)&r[2];
        const __half2* p3 = (const __half2*)&r[3];
#pragma unroll
        for (int q = 0; q < 4; q++) {
            __half2 t01 = __hfma2(p1[q], eh[1], __hmul2(p0[q], eh[0]));
            __half2 t23 = __hfma2(p3[q], eh[3], __hmul2(p2[q], eh[2]));
            float2 f01 = __half22float2(t01);
            float2 f23 = __half22float2(t23);
            acc[2 * q]     += f01.x + f23.x;
            acc[2 * q + 1] += f01.y + f23.y;
        }
        j = jn;
        cur = nxt;
#pragma unroll
        for (int k = 0; k < 4; k++) s[k] = sn[k];
    }
    for (; j < end; j++) {
        int s0 = __ldg(&g_csr_src[j]);
        float e0 = __expf(lrelu(__ldg(&g_as1[s0 * H1 + head]) + adh));
        den += e0;
        uint4 r0 = __ldg((const uint4*)(hbase + (size_t)s0 * D1));
        const __half2* p = (const __half2*)&r0;
#pragma unroll
        for (int q = 0; q < 4; q++) {
            float2 f = __half22float2(p[q]);
            acc[2 * q]     += e0 * f.x;
            acc[2 * q + 1] += e0 * f.y;
        }
    }

    float inv = 1.f / (den + 1e-16f);
    const float* bb = b1 + lane * 8;
    __half2 o[4];
#pragma unroll
    for (int q = 0; q < 4; q++) {
        float f0 = fmaxf(acc[2 * q]     * inv + bb[2 * q],     0.f);
        float f1 = fmaxf(acc[2 * q + 1] * inv + bb[2 * q + 1], 0.f);
        o[q] = __floats2half2_rn(f0, f1);
    }
    *(uint4*)(g_out1 + (size_t)node * D1 + lane * 8) = *(uint4*)o;
}

// ---- layer2 aggregation: warp per node, batch-4 + index prefetch (R13) ----
__global__ void aggr2(float* __restrict__ out, const float* __restrict__ b2) {
    int w    = (blockIdx.x * blockDim.x + threadIdx.x) >> 5;
    int lane = threadIdx.x & 31;
    if (w >= NN) return;
    float adh = g_ad2[w];
    int beg = g_row[w], end = g_row[w + 1];

    float den = 0.f;
    float2 acc = {0.f, 0.f};
    int j = beg;
    int s[4];
    bool cur = (j + 3 < end);
    if (cur) {
#pragma unroll
        for (int k = 0; k < 4; k++) s[k] = __ldg(&g_csr_src[j + k]);
    }
    while (cur) {
        int jn = j + 4;
        bool nxt = (jn + 3 < end);
        int sn[4];
        if (nxt) {
#pragma unroll
            for (int k = 0; k < 4; k++) sn[k] = __ldg(&g_csr_src[jn + k]);
        }
        __half2 hv[4];
#pragma unroll
        for (int k = 0; k < 4; k++)
            hv[k] = __ldg((const __half2*)(g_h2 + (size_t)s[k] * D2) + lane);
        float e[4];
#pragma unroll
        for (int k = 0; k < 4; k++)
            e[k] = __expf(lrelu(__ldg(&g_as2[s[k]]) + adh));
#pragma unroll
        for (int k = 0; k < 4; k++) {
            den += e[k];
            float2 f = __half22float2(hv[k]);
            acc.x += e[k] * f.x;
            acc.y += e[k] * f.y;
        }
        j = jn;
        cur = nxt;
#pragma unroll
        for (int k = 0; k < 4; k++) s[k] = sn[k];
    }
    for (; j < end; j++) {
        int s0 = __ldg(&g_csr_src[j]);
        float e0 = __expf(lrelu(__ldg(&g_as2[s0]) + adh));
        den += e0;
        float2 f = __half22float2(__ldg((const __half2*)(g_h2 + (size_t)s0 * D2) + lane));
        acc.x += e0 * f.x;
        acc.y += e0 * f.y;
    }
    float inv = 1.f / (den + 1e-16f);
    float2 bv = ((const float2*)b2)[lane];
    ((float2*)(out + (size_t)w * D2))[lane] =
        make_float2(acc.x * inv + bv.x, acc.y * inv + bv.y);
}

extern "C" void kernel_launch(void* const* d_in, const int* in_sizes, int n_in,
                              void* d_out, int out_size) {
    const float* x   = (const float*)d_in[0];
    const int*   ei  = (const int*)  d_in[1];
    const float* W1  = (const float*)d_in[2];
    const float* as1 = (const float*)d_in[3];
    const float* ad1 = (const float*)d_in[4];
    const float* b1  = (const float*)d_in[5];
    const float* W2  = (const float*)d_in[6];
    const float* as2 = (const float*)d_in[7];
    const float* ad2 = (const float*)d_in[8];
    const float* b2  = (const float*)d_in[9];
    float* out = (float*)d_out;

    static cudaStream_t s2 = nullptr;
    static cudaEvent_t evFork = nullptr, evJoin = nullptr, evA0 = nullptr, evG0 = nullptr;
    if (!s2) {
        cudaStreamCreateWithFlags(&s2, cudaStreamNonBlocking);
        cudaEventCreateWithFlags(&evFork, cudaEventDisableTiming);
        cudaEventCreateWithFlags(&evJoin, cudaEventDisableTiming);
        cudaEventCreateWithFlags(&evA0,   cudaEventDisableTiming);
        cudaEventCreateWithFlags(&evG0,   cudaEventDisableTiming);
    }

    void *p_h1, *p_out1, *p_h2, *p_as1, *p_ad1, *p_as2, *p_ad2, *p_cnt;
    cudaGetSymbolAddress(&p_h1,   g_h1);
    cudaGetSymbolAddress(&p_out1, g_out1);
    cudaGetSymbolAddress(&p_h2,   g_h2);
    cudaGetSymbolAddress(&p_as1,  g_as1);
    cudaGetSymbolAddress(&p_ad1,  g_ad1);
    cudaGetSymbolAddress(&p_as2,  g_as2);
    cudaGetSymbolAddress(&p_ad2,  g_ad2);
    cudaGetSymbolAddress(&p_cnt,  g_cnt);

    // ---- fork: CSR build on s2, concurrent with GEMM1 ----
    cudaEventRecord(evFork, 0);
    cudaStreamWaitEvent(s2, evFork, 0);
    cudaMemsetAsync(p_cnt, 0, NN * sizeof(int), s2);
    hist<<<(NE / 4 + 255) / 256, 256, 0, s2>>>(ei);
    scan_fused<<<1, 1024, 0, s2>>>();
    scatter<<<(NE / 2 + NN + 255) / 256, 256, 0, s2>>>(ei);
    cudaEventRecord(evJoin, s2);

    // main stream: GEMM1 (fp16 HMMA) + fused scores
    {
        dim3 grid(D1 / 64, (NN + 127) / 128);
        gemm1_fused<<<grid, 256>>>(x, W1, (__half*)p_h1, as1, ad1,
                                   (float*)p_as1, (float*)p_ad1);
    }
    cudaStreamWaitEvent(0, evJoin, 0);

    // uneven pipelined halves:
    // aggr1(H0=37.5k) -> {gemm2(H0) on s2 || aggr1(H1=12.5k)} -> gemm2(H1)
    aggr1<<<(NH0 + 7) / 8, 256>>>(b1, 0, NH0);
    cudaEventRecord(evA0, 0);

    cudaStreamWaitEvent(s2, evA0, 0);
    {
        dim3 grid(1, (NH0 + 127) / 128);
        gemm2_fused<<<grid, 256, 0, s2>>>((const __half*)p_out1, W2, (__half*)p_h2,
                                          as2, ad2, (float*)p_as2, (float*)p_ad2,
                                          0, NH0);
    }
    cudaEventRecord(evG0, s2);

    aggr1<<<(NH1 + 7) / 8, 256>>>(b1, NH0, NH1);
    {
        dim3 grid(1, (NH1 + 127) / 128);
        gemm2_fused<<<grid, 256>>>((const __half*)p_out1, W2, (__half*)p_h2,
                                   as2, ad2, (float*)p_as2, (float*)p_ad2,
                                   NH0, NH1);
    }
    cudaStreamWaitEvent(0, evG0, 0);
    aggr2<<<(NN + 7) / 8, 256>>>(out, b2);
}

// round 17
// speedup vs baseline: 1.0908x; 1.0260x over previous
#include <cuda_runtime.h>
#include <cuda_fp16.h>

#define NN   50000
#define NE   800000
#define ET   (NE + NN)
#define INC  128
#define HID  32
#define H1   8
#define D1   256
#define D2   64
#define NH0  37500
#define NH1  (NN - NH0)

__device__ __forceinline__ float lrelu(float v) { return v > 0.f ? v : 0.2f * v; }

// ---- scratch ----
__device__ __half   g_h1[(size_t)NN * D1];
__device__ __half   g_out1[(size_t)NN * D1];
__device__ float    g_as1[NN * H1];
__device__ float    g_ad1[NN * H1];
__device__ __half   g_h2[(size_t)NN * D2];
__device__ float    g_as2[NN];
__device__ float    g_ad2[NN];

// CSR
__device__ int g_cnt[NN];
__device__ int g_row[NN + 1];
__device__ int g_cur[NN];
__device__ int g_csr_src[ET];

// ============================================================
// CSR build
// ============================================================
__global__ void hist(const int* __restrict__ ei) {
    int i = blockIdx.x * blockDim.x + threadIdx.x;
    if (i * 4 >= NE) return;
    int4 d = *(const int4*)&ei[NE + i * 4];
    atomicAdd(&g_cnt[d.x], 1);
    atomicAdd(&g_cnt[d.y], 1);
    atomicAdd(&g_cnt[d.z], 1);
    atomicAdd(&g_cnt[d.w], 1);
}
__global__ void scan_fused() {
    __shared__ int wsum[32];
    __shared__ int s_carry;
    const int CH = 2048;
    int t = threadIdx.x, lane = t & 31, wid = t >> 5;
    if (t == 0) s_carry = 0;
    __syncthreads();
    for (int chunk = 0; chunk < (NN + CH - 1) / CH; chunk++) {
        int i0 = chunk * CH + 2 * t;
        int v0 = (i0     < NN) ? g_cnt[i0]     + 1 : 0;
        int v1 = (i0 + 1 < NN) ? g_cnt[i0 + 1] + 1 : 0;
        int p = v0 + v1;
        int x = p;
#pragma unroll
        for (int o = 1; o < 32; o <<= 1) {
            int y = __shfl_up_sync(0xffffffffu, x, o);
            if (lane >= o) x += y;
        }
        if (lane == 31) wsum[wid] = x;
        __syncthreads();
        if (wid == 0) {
            int w = wsum[lane];
#pragma unroll
            for (int o = 1; o < 32; o <<= 1) {
                int y = __shfl_up_sync(0xffffffffu, w, o);
                if (lane >= o) w += y;
            }
            wsum[lane] = w;
        }
        __syncthreads();
        int base = s_carry + (wid ? wsum[wid - 1] : 0);
        int excl = base + x - p;
        if (i0     < NN) { g_row[i0]     = excl;      g_cur[i0]     = excl; }
        if (i0 + 1 < NN) { g_row[i0 + 1] = excl + v0; g_cur[i0 + 1] = excl + v0; }
        __syncthreads();
        if (t == blockDim.x - 1) s_carry = base + x;
        __syncthreads();
    }
    if (t == 0) g_row[NN] = ET;
}
__global__ void scatter(const int* __restrict__ ei) {
    int i = blockIdx.x * blockDim.x + threadIdx.x;
    if (i < NE / 2) {
        int2 s = *(const int2*)&ei[2 * i];
        int2 d = *(const int2*)&ei[NE + 2 * i];
        int p0 = atomicAdd(&g_cur[d.x], 1); g_csr_src[p0] = s.x;
        int p1 = atomicAdd(&g_cur[d.y], 1); g_csr_src[p1] = s.y;
    } else {
        int e = i - NE / 2;
        if (e < NN) {
            int p = atomicAdd(&g_cur[e], 1);
            g_csr_src[p] = e;
        }
    }
}

// ============================================================
// fp16 MMA + ldmatrix helpers
// ============================================================
__device__ __forceinline__ void mma_f16(float c[4], const unsigned a[4],
                                        const unsigned b[2]) {
    asm volatile(
        "mma.sync.aligned.m16n8k16.row.col.f32.f16.f16.f32 "
        "{%0,%1,%2,%3}, {%4,%5,%6,%7}, {%8,%9}, {%0,%1,%2,%3};"
        : "+f"(c[0]), "+f"(c[1]), "+f"(c[2]), "+f"(c[3])
        : "r"(a[0]), "r"(a[1]), "r"(a[2]), "r"(a[3]), "r"(b[0]), "r"(b[1]));
}
__device__ __forceinline__ void ldmA(unsigned a[4], const void* p) {
    unsigned addr = (unsigned)__cvta_generic_to_shared(p);
    asm volatile(
        "ldmatrix.sync.aligned.m8n8.x4.shared.b16 {%0,%1,%2,%3}, [%4];"
        : "=r"(a[0]), "=r"(a[1]), "=r"(a[2]), "=r"(a[3]) : "r"(addr));
}

#define ASTRIDE 20
#define BSTRIDE 72

// ============================================================
// GEMM1 fused (fp16 HMMA + ldmatrix A): h1 = x @ W1 + att scores.
// Register-staged double buffering of k-tiles.
// ============================================================
__global__ void gemm1_fused(const float* __restrict__ A, const float* __restrict__ B,
                            __half* __restrict__ C,
                            const float* __restrict__ atts,
                            const float* __restrict__ attd,
                            float* __restrict__ as_, float* __restrict__ ad_) {
    const int BM = 128, BN = 64, BK = 32, M = NN, N = D1, K = INC;
    const int NT = K / BK;
    __shared__ __half2 As2[BM][ASTRIDE];
    __shared__ __half2 Bs2[BK / 2][BSTRIDE];

    int t = threadIdx.x, warp = t >> 5, lane = t & 31;
    int wm = warp >> 1, wn = warp & 1;
    int g = lane >> 2, t4 = lane & 3;
    int lrow = lane & 15, lkk = (lane >> 4) << 2;   // ldmatrix addressing
    int row0 = blockIdx.y * BM, col0 = blockIdx.x * BN;

    float acc[2][4][4] = {};

    float4 va[4];
    float bl[4], bh[4];

    {
#pragma unroll
        for (int i = 0; i < 4; i++) {
            int idx = t + i * 256;
            int r = idx >> 3, c4 = (idx & 7) * 4;
            int gr = row0 + r;
            va[i] = (gr < M) ? *(const float4*)&A[(size_t)gr * K + c4]
                             : make_float4(0.f, 0.f, 0.f, 0.f);
        }
#pragma unroll
        for (int i = 0; i < 4; i++) {
            int idx = t + i * 256;
            int kk = idx >> 6, n = idx & 63;
            bl[i] = B[(size_t)(2 * kk) * N + col0 + n];
            bh[i] = B[(size_t)(2 * kk + 1) * N + col0 + n];
        }
    }

    for (int it = 0; it < NT; it++) {
#pragma unroll
        for (int i = 0; i < 4; i++) {
            int idx = t + i * 256;
            int r = idx >> 3, c4 = (idx & 7) * 4;
            __half2 h0 = __floats2half2_rn(va[i].x, va[i].y);
            __half2 h1v = __floats2half2_rn(va[i].z, va[i].w);
            *(uint2*)&As2[r][c4 / 2] =
                make_uint2(*(unsigned*)&h0, *(unsigned*)&h1v);
        }
#pragma unroll
        for (int i = 0; i < 4; i++) {
            int idx = t + i * 256;
            int kk = idx >> 6, n = idx & 63;
            Bs2[kk][n] = __floats2half2_rn(bl[i], bh[i]);
        }
        __syncthreads();

        if (it + 1 < NT) {
            int kt = (it + 1) * BK;
#pragma unroll
            for (int i = 0; i < 4; i++) {
                int idx = t + i * 256;
                int r = idx >> 3, c4 = (idx & 7) * 4;
                int gr = row0 + r;
                va[i] = (gr < M) ? *(const float4*)&A[(size_t)gr * K + kt + c4]
                                 : make_float4(0.f, 0.f, 0.f, 0.f);
            }
#pragma unroll
            for (int i = 0; i < 4; i++) {
                int idx = t + i * 256;
                int kk = idx >> 6, n = idx & 63;
                bl[i] = B[(size_t)(kt + 2 * kk) * N + col0 + n];
                bh[i] = B[(size_t)(kt + 2 * kk + 1) * N + col0 + n];
            }
        }

#pragma unroll
        for (int k0 = 0; k0 < BK; k0 += 16) {
            int kk = k0 >> 1;
            unsigned a[2][4], b[4][2];
#pragma unroll
            for (int mi = 0; mi < 2; mi++) {
                int mb = wm * 32 + mi * 16;
                ldmA(a[mi], &As2[mb + lrow][kk + lkk]);
            }
#pragma unroll
            for (int ni = 0; ni < 4; ni++) {
                int nb = wn * 32 + ni * 8;
                b[ni][0] = *(const unsigned*)&Bs2[kk + t4][nb + g];
                b[ni][1] = *(const unsigned*)&Bs2[kk + 4 + t4][nb + g];
            }
#pragma unroll
            for (int mi = 0; mi < 2; mi++)
#pragma unroll
                for (int ni = 0; ni < 4; ni++)
                    mma_f16(acc[mi][ni], a[mi], b[ni]);
        }
        __syncthreads();
    }

#pragma unroll
    for (int mi = 0; mi < 2; mi++)
#pragma unroll
        for (int ni = 0; ni < 4; ni++) {
            int col = col0 + wn * 32 + ni * 8 + t4 * 2;
            int r0 = row0 + wm * 32 + mi * 16 + g, r1 = r0 + 8;
            if (r0 < M)
                *(__half2*)&C[(size_t)r0 * N + col] =
                    __floats2half2_rn(acc[mi][ni][0], acc[mi][ni][1]);
            if (r1 < M)
                *(__half2*)&C[(size_t)r1 * N + col] =
                    __floats2half2_rn(acc[mi][ni][2], acc[mi][ni][3]);
        }

    int hidx = (col0 + wn * 32) >> 5;
    const float* aw = atts + hidx * HID;
    const float* dw = attd + hidx * HID;
#pragma unroll
    for (int mi = 0; mi < 2; mi++) {
        float ss0 = 0.f, dd0 = 0.f, ss1 = 0.f, dd1 = 0.f;
#pragma unroll
        for (int ni = 0; ni < 4; ni++) {
            int c = ni * 8 + t4 * 2;
            float a0 = aw[c], a1 = aw[c + 1];
            float d0 = dw[c], d1 = dw[c + 1];
            ss0 += acc[mi][ni][0] * a0 + acc[mi][ni][1] * a1;
            dd0 += acc[mi][ni][0] * d0 + acc[mi][ni][1] * d1;
            ss1 += acc[mi][ni][2] * a0 + acc[mi][ni][3] * a1;
            dd1 += acc[mi][ni][2] * d0 + acc[mi][ni][3] * d1;
        }
#pragma unroll
        for (int o = 1; o < 4; o <<= 1) {
            ss0 += __shfl_xor_sync(0xffffffffu, ss0, o);
            dd0 += __shfl_xor_sync(0xffffffffu, dd0, o);
            ss1 += __shfl_xor_sync(0xffffffffu, ss1, o);
            dd1 += __shfl_xor_sync(0xffffffffu, dd1, o);
        }
        if (t4 == 0) {
            int r0 = row0 + wm * 32 + mi * 16 + g, r1 = r0 + 8;
            if (r0 < M) { as_[r0 * H1 + hidx] = ss0; ad_[r0 * H1 + hidx] = dd0; }
            if (r1 < M) { as_[r1 * H1 + hidx] = ss1; ad_[r1 * H1 + hidx] = dd1; }
        }
    }
}

// ============================================================
// GEMM2 fused (fp16 HMMA + ldmatrix A), row-range parametrized.
// ============================================================
__global__ void gemm2_fused(const __half* __restrict__ A, const float* __restrict__ B,
                            __half* __restrict__ C,
                            const float* __restrict__ atts,
                            const float* __restrict__ attd,
                            float* __restrict__ as_, float* __restrict__ ad_,
                            int row_base, int nrows) {
    const int BM = 128, BN = 64, BK = 32, N = D2, K = D1;
    const int Mlim = row_base + nrows;
    __shared__ __half2 As2[BM][ASTRIDE];
    __shared__ __half2 Bs2[BK / 2][BSTRIDE];
    __shared__ float sS[BM][2], sD[BM][2];

    int t = threadIdx.x, warp = t >> 5, lane = t & 31;
    int wm = warp >> 1, wn = warp & 1;
    int g = lane >> 2, t4 = lane & 3;
    int lrow = lane & 15, lkk = (lane >> 4) << 2;
    int row0 = row_base + blockIdx.y * BM;

    float acc[2][4][4] = {};

    for (int kt = 0; kt < K; kt += BK) {
#pragma unroll
        for (int i = 0; i < 2; i++) {
            int idx = t + i * 256;
            int r = idx >> 2, c8 = (idx & 3) * 8;
            int gr = row0 + r;
            uint4 raw = (gr < Mlim) ? *(const uint4*)&A[(size_t)gr * K + kt + c8]
                                    : make_uint4(0, 0, 0, 0);
            *(uint2*)&As2[r][c8 / 2]     = make_uint2(raw.x, raw.y);
            *(uint2*)&As2[r][c8 / 2 + 2] = make_uint2(raw.z, raw.w);
        }
#pragma unroll
        for (int i = 0; i < 4; i++) {
            int idx = t + i * 256;
            int kk = idx >> 6, n = idx & 63;
            float lo = B[(size_t)(kt + 2 * kk) * N + n];
            float hi = B[(size_t)(kt + 2 * kk + 1) * N + n];
            Bs2[kk][n] = __floats2half2_rn(lo, hi);
        }
        __syncthreads();
#pragma unroll
        for (int k0 = 0; k0 < BK; k0 += 16) {
            int kk = k0 >> 1;
            unsigned a[2][4], b[4][2];
#pragma unroll
            for (int mi = 0; mi < 2; mi++) {
                int mb = wm * 32 + mi * 16;
                ldmA(a[mi], &As2[mb + lrow][kk + lkk]);
            }
#pragma unroll
            for (int ni = 0; ni < 4; ni++) {
                int nb = wn * 32 + ni * 8;
                b[ni][0] = *(const unsigned*)&Bs2[kk + t4][nb + g];
                b[ni][1] = *(const unsigned*)&Bs2[kk + 4 + t4][nb + g];
            }
#pragma unroll
            for (int mi = 0; mi < 2; mi++)
#pragma unroll
                for (int ni = 0; ni < 4; ni++)
                    mma_f16(acc[mi][ni], a[mi], b[ni]);
        }
        __syncthreads();
    }

#pragma unroll
    for (int mi = 0; mi < 2; mi++)
#pragma unroll
        for (int ni = 0; ni < 4; ni++) {
            int col = wn * 32 + ni * 8 + t4 * 2;
            int r0 = row0 + wm * 32 + mi * 16 + g, r1 = r0 + 8;
            if (r0 < Mlim)
                *(__half2*)&C[(size_t)r0 * N + col] =
                    __floats2half2_rn(acc[mi][ni][0], acc[mi][ni][1]);
            if (r1 < Mlim)
                *(__half2*)&C[(size_t)r1 * N + col] =
                    __floats2half2_rn(acc[mi][ni][2], acc[mi][ni][3]);
        }

#pragma unroll
    for (int mi = 0; mi < 2; mi++) {
        float ss0 = 0.f, dd0 = 0.f, ss1 = 0.f, dd1 = 0.f;
#pragma unroll
        for (int ni = 0; ni < 4; ni++) {
            int c = wn * 32 + ni * 8 + t4 * 2;
            float a0 = atts[c], a1 = atts[c + 1];
            float d0 = attd[c], d1 = attd[c + 1];
            ss0 += acc[mi][ni][0] * a0 + acc[mi][ni][1] * a1;
            dd0 += acc[mi][ni][0] * d0 + acc[mi][ni][1] * d1;
            ss1 += acc[mi][ni][2] * a0 + acc[mi][ni][3] * a1;
            dd1 += acc[mi][ni][2] * d0 + acc[mi][ni][3] * d1;
        }
#pragma unroll
        for (int o = 1; o < 4; o <<= 1) {
            ss0 += __shfl_xor_sync(0xffffffffu, ss0, o);
            dd0 += __shfl_xor_sync(0xffffffffu, dd0, o);
            ss1 += __shfl_xor_sync(0xffffffffu, ss1, o);
            dd1 += __shfl_xor_sync(0xffffffffu, dd1, o);
        }
        if (t4 == 0) {
            int lr0 = wm * 32 + mi * 16 + g, lr1 = lr0 + 8;
            sS[lr0][wn] = ss0; sD[lr0][wn] = dd0;
            sS[lr1][wn] = ss1; sD[lr1][wn] = dd1;
        }
    }
    __syncthreads();
    if (t < BM) {
        int gr = row0 + t;
        if (gr < Mlim) {
            as_[gr] = sS[t][0] + sS[t][1];
            ad_[gr] = sD[t][0] + sD[t][1];
        }
    }
}

// ============================================================
// layer1 aggregation: warp per node, own-head exp, half2 pair
// accumulation (R13 shape, untouched).
// ============================================================
__global__ void aggr1(const float* __restrict__ b1, int node_base, int nnodes) {
    int gw   = (blockIdx.x * blockDim.x + threadIdx.x) >> 5;
    int lane = threadIdx.x & 31;
    if (gw >= nnodes) return;
    int node = node_base + gw;
    int head = lane >> 2;

    float adh = g_ad1[node * H1 + head];
    int beg = g_row[node], end = g_row[node + 1];

    float den = 0.f;
    float acc[8] = {};
    const __half* hbase = g_h1 + lane * 8;

    int j = beg;
    int s[4];
    bool cur = (j + 3 < end);
    if (cur) {
#pragma unroll
        for (int k = 0; k < 4; k++) s[k] = __ldg(&g_csr_src[j + k]);
    }
    while (cur) {
        int jn = j + 4;
        bool nxt = (jn + 3 < end);
        int sn[4];
        if (nxt) {
#pragma unroll
            for (int k = 0; k < 4; k++) sn[k] = __ldg(&g_csr_src[jn + k]);
        }
        uint4 r[4];
#pragma unroll
        for (int k = 0; k < 4; k++)
            r[k] = __ldg((const uint4*)(hbase + (size_t)s[k] * D1));
        float e[4];
#pragma unroll
        for (int k = 0; k < 4; k++)
            e[k] = __expf(lrelu(__ldg(&g_as1[s[k] * H1 + head]) + adh));
        den += (e[0] + e[1]) + (e[2] + e[3]);
        __half2 eh[4];
#pragma unroll
        for (int k = 0; k < 4; k++)
            eh[k] = __float2half2_rn(e[k]);
        const __half2* p0 = (const __half2*)&r[0];
        const __half2* p1 = (const __half2*)&r[1];
        const __half2* p2 = (const __half2*)&r[2];
        const __half2* p3 = (const __half2*)&r[3];
#pragma unroll
        for (int q = 0; q < 4; q++) {
            __half2 t01 = __hfma2(p1[q], eh[1], __hmul2(p0[q], eh[0]));
            __half2 t23 = __hfma2(p3[q], eh[3], __hmul2(p2[q], eh[2]));
            float2 f01 = __half22float2(t01);
            float2 f23 = __half22float2(t23);
            acc[2 * q]     += f01.x + f23.x;
            acc[2 * q + 1] += f01.y + f23.y;
        }
        j = jn;
        cur = nxt;
#pragma unroll
        for (int k = 0; k < 4; k++) s[k] = sn[k];
    }
    for (; j < end; j++) {
        int s0 = __ldg(&g_csr_src[j]);
        float e0 = __expf(lrelu(__ldg(&g_as1[s0 * H1 + head]) + adh));
        den += e0;
        uint4 r0 = __ldg((const uint4*)(hbase + (size_t)s0 * D1));
        const __half2* p = (const __half2*)&r0;
#pragma unroll
        for (int q = 0; q < 4; q++) {
            float2 f = __half22float2(p[q]);
            acc[2 * q]     += e0 * f.x;
            acc[2 * q + 1] += e0 * f.y;
        }
    }

    float inv = 1.f / (den + 1e-16f);
    const float* bb = b1 + lane * 8;
    __half2 o[4];
#pragma unroll
    for (int q = 0; q < 4; q++) {
        float f0 = fmaxf(acc[2 * q]     * inv + bb[2 * q],     0.f);
        float f1 = fmaxf(acc[2 * q + 1] * inv + bb[2 * q + 1], 0.f);
        o[q] = __floats2half2_rn(f0, f1);
    }
    *(uint4*)(g_out1 + (size_t)node * D1 + lane * 8) = *(uint4*)o;
}

// ---- layer2 aggregation: warp per node, batch-4 + index prefetch (R13) ----
__global__ void aggr2(float* __restrict__ out, const float* __restrict__ b2) {
    int w    = (blockIdx.x * blockDim.x + threadIdx.x) >> 5;
    int lane = threadIdx.x & 31;
    if (w >= NN) return;
    float adh = g_ad2[w];
    int beg = g_row[w], end = g_row[w + 1];

    float den = 0.f;
    float2 acc = {0.f, 0.f};
    int j = beg;
    int s[4];
    bool cur = (j + 3 < end);
    if (cur) {
#pragma unroll
        for (int k = 0; k < 4; k++) s[k] = __ldg(&g_csr_src[j + k]);
    }
    while (cur) {
        int jn = j + 4;
        bool nxt = (jn + 3 < end);
        int sn[4];
        if (nxt) {
#pragma unroll
            for (int k = 0; k < 4; k++) sn[k] = __ldg(&g_csr_src[jn + k]);
        }
        __half2 hv[4];
#pragma unroll
        for (int k = 0; k < 4; k++)
            hv[k] = __ldg((const __half2*)(g_h2 + (size_t)s[k] * D2) + lane);
        float e[4];
#pragma unroll
        for (int k = 0; k < 4; k++)
            e[k] = __expf(lrelu(__ldg(&g_as2[s[k]]) + adh));
#pragma unroll
        for (int k = 0; k < 4; k++) {
            den += e[k];
            float2 f = __half22float2(hv[k]);
            acc.x += e[k] * f.x;
            acc.y += e[k] * f.y;
        }
        j = jn;
        cur = nxt;
#pragma unroll
        for (int k = 0; k < 4; k++) s[k] = sn[k];
    }
    for (; j < end; j++) {
        int s0 = __ldg(&g_csr_src[j]);
        float e0 = __expf(lrelu(__ldg(&g_as2[s0]) + adh));
        den += e0;
        float2 f = __half22float2(__ldg((const __half2*)(g_h2 + (size_t)s0 * D2) + lane));
        acc.x += e0 * f.x;
        acc.y += e0 * f.y;
    }
    float inv = 1.f / (den + 1e-16f);
    float2 bv = ((const float2*)b2)[lane];
    ((float2*)(out + (size_t)w * D2))[lane] =
        make_float2(acc.x * inv + bv.x, acc.y * inv + bv.y);
}

extern "C" void kernel_launch(void* const* d_in, const int* in_sizes, int n_in,
                              void* d_out, int out_size) {
    const float* x   = (const float*)d_in[0];
    const int*   ei  = (const int*)  d_in[1];
    const float* W1  = (const float*)d_in[2];
    const float* as1 = (const float*)d_in[3];
    const float* ad1 = (const float*)d_in[4];
    const float* b1  = (const float*)d_in[5];
    const float* W2  = (const float*)d_in[6];
    const float* as2 = (const float*)d_in[7];
    const float* ad2 = (const float*)d_in[8];
    const float* b2  = (const float*)d_in[9];
    float* out = (float*)d_out;

    static cudaStream_t s2 = nullptr;
    static cudaEvent_t evFork = nullptr, evJoin = nullptr, evA0 = nullptr, evG0 = nullptr;
    if (!s2) {
        cudaStreamCreateWithFlags(&s2, cudaStreamNonBlocking);
        cudaEventCreateWithFlags(&evFork, cudaEventDisableTiming);
        cudaEventCreateWithFlags(&evJoin, cudaEventDisableTiming);
        cudaEventCreateWithFlags(&evA0,   cudaEventDisableTiming);
        cudaEventCreateWithFlags(&evG0,   cudaEventDisableTiming);
    }

    void *p_h1, *p_out1, *p_h2, *p_as1, *p_ad1, *p_as2, *p_ad2, *p_cnt;
    cudaGetSymbolAddress(&p_h1,   g_h1);
    cudaGetSymbolAddress(&p_out1, g_out1);
    cudaGetSymbolAddress(&p_h2,   g_h2);
    cudaGetSymbolAddress(&p_as1,  g_as1);
    cudaGetSymbolAddress(&p_ad1,  g_ad1);
    cudaGetSymbolAddress(&p_as2,  g_as2);
    cudaGetSymbolAddress(&p_ad2,  g_ad2);
    cudaGetSymbolAddress(&p_cnt,  g_cnt);

    // ---- fork: CSR build on s2, concurrent with GEMM1 ----
    cudaEventRecord(evFork, 0);
    cudaStreamWaitEvent(s2, evFork, 0);
    cudaMemsetAsync(p_cnt, 0, NN * sizeof(int), s2);
    hist<<<(NE / 4 + 255) / 256, 256, 0, s2>>>(ei);
    scan_fused<<<1, 1024, 0, s2>>>();
    scatter<<<(NE / 2 + NN + 255) / 256, 256, 0, s2>>>(ei);
    cudaEventRecord(evJoin, s2);

    // main stream: GEMM1 (fp16 HMMA + ldmatrix) + fused scores
    {
        dim3 grid(D1 / 64, (NN + 127) / 128);
        gemm1_fused<<<grid, 256>>>(x, W1, (__half*)p_h1, as1, ad1,
                                   (float*)p_as1, (float*)p_ad1);
    }
    cudaStreamWaitEvent(0, evJoin, 0);

    // uneven pipelined halves:
    // aggr1(H0=37.5k) -> {gemm2(H0) on s2 || aggr1(H1=12.5k)} -> gemm2(H1)
    aggr1<<<(NH0 + 7) / 8, 256>>>(b1, 0, NH0);
    cudaEventRecord(evA0, 0);

    cudaStreamWaitEvent(s2, evA0, 0);
    {
        dim3 grid(1, (NH0 + 127) / 128);
        gemm2_fused<<<grid, 256, 0, s2>>>((const __half*)p_out1, W2, (__half*)p_h2,
                                          as2, ad2, (float*)p_as2, (float*)p_ad2,
                                          0, NH0);
    }
    cudaEventRecord(evG0, s2);

    aggr1<<<(NH1 + 7) / 8, 256>>>(b1, NH0, NH1);
    {
        dim3 grid(1, (NH1 + 127) / 128);
        gemm2_fused<<<grid, 256>>>((const __half*)p_out1, W2, (__half*)p_h2,
                                   as2, ad2, (float*)p_as2, (float*)p_ad2,
                                   NH0, NH1);
    }
    cudaStreamWaitEvent(0, evG0, 0);
    aggr2<<<(NN + 7) / 8, 256>>>(out, b2);
}